// round 4
// baseline (speedup 1.0000x reference)
#include <cuda_runtime.h>
#include <math.h>

// Problem constants
#define BB   4
#define SS   2048
#define DD   1024
#define HH   16
#define DHH  64
#define MM   (BB * SS)          // 8192 rows
#define MASKV (-1000000.0f)

// Scratch (device globals: allocation-free rule)
__device__ float g_Qh[(size_t)MM * DD];  // [B,H,S,DH] head-split
__device__ float g_Kh[(size_t)MM * DD];
__device__ float g_Vh[(size_t)MM * DD];
__device__ float g_Oc[(size_t)MM * DD];  // [B,S,D] concat-head attention output

// ---------------------------------------------------------------------------
// NT GEMM: C[m,n] = sum_k A[m,k] * W[n,k]
// A: [M,1024] row-major, W: [1024,1024] row-major (out_features, in_features)
// mode 0: write head-split [B,H,S,DH];  mode 1: write row-major [M,1024]
// 128x128 tile, BK=16, 256 threads, 8x8 per thread.
// ---------------------------------------------------------------------------
__global__ __launch_bounds__(256) void gemm_nt(const float* __restrict__ A,
                                               const float* __restrict__ W,
                                               float* __restrict__ C,
                                               int mode)
{
    __shared__ float As[16][132];
    __shared__ float Bs[16][132];

    const int tid = threadIdx.x;
    const int bm  = blockIdx.y * 128;
    const int bn  = blockIdx.x * 128;
    const int tm  = (tid >> 4) << 3;   // (tid/16)*8
    const int tn  = (tid & 15) << 3;   // (tid%16)*8

    float acc[8][8];
#pragma unroll
    for (int i = 0; i < 8; i++)
#pragma unroll
        for (int j = 0; j < 8; j++) acc[i][j] = 0.0f;

    for (int kt = 0; kt < DD; kt += 16) {
        // Load 128x16 tiles of A and W, transposed into shared: As[k][m]
#pragma unroll
        for (int it = 0; it < 2; it++) {
            int idx = tid + it * 256;          // 0..511 float4 units
            int row = idx >> 2;                // 0..127
            int kc  = (idx & 3) << 2;          // 0,4,8,12
            float4 va = *(const float4*)(A + (size_t)(bm + row) * DD + kt + kc);
            As[kc + 0][row] = va.x;
            As[kc + 1][row] = va.y;
            As[kc + 2][row] = va.z;
            As[kc + 3][row] = va.w;
            float4 vb = *(const float4*)(W + (size_t)(bn + row) * DD + kt + kc);
            Bs[kc + 0][row] = vb.x;
            Bs[kc + 1][row] = vb.y;
            Bs[kc + 2][row] = vb.z;
            Bs[kc + 3][row] = vb.w;
        }
        __syncthreads();

#pragma unroll
        for (int k = 0; k < 16; k++) {
            float a[8], b[8];
#pragma unroll
            for (int i = 0; i < 8; i++) a[i] = As[k][tm + i];
#pragma unroll
            for (int j = 0; j < 8; j++) b[j] = Bs[k][tn + j];
#pragma unroll
            for (int i = 0; i < 8; i++)
#pragma unroll
                for (int j = 0; j < 8; j++)
                    acc[i][j] = fmaf(a[i], b[j], acc[i][j]);
        }
        __syncthreads();
    }

    if (mode == 0) {
        // head-split epilogue: (m,n) -> [b, h, s, dh]
#pragma unroll
        for (int i = 0; i < 8; i++) {
            int m  = bm + tm + i;
            int b_ = m >> 11;              // / S
            int s_ = m & (SS - 1);
#pragma unroll
            for (int j = 0; j < 8; j++) {
                int n   = bn + tn + j;
                int h_  = n >> 6;
                int dh  = n & 63;
                C[(((size_t)b_ * HH + h_) * SS + s_) * DHH + dh] = acc[i][j];
            }
        }
    } else {
#pragma unroll
        for (int i = 0; i < 8; i++) {
            size_t off = (size_t)(bm + tm + i) * DD + bn + tn;
            float4 v0 = make_float4(acc[i][0], acc[i][1], acc[i][2], acc[i][3]);
            float4 v1 = make_float4(acc[i][4], acc[i][5], acc[i][6], acc[i][7]);
            *(float4*)(C + off)     = v0;
            *(float4*)(C + off + 4) = v1;
        }
    }
}

// ---------------------------------------------------------------------------
// Flash attention, fp32. One block = one (b, h, 64-row Q tile).
// 256 threads; score/PV tiles 64x64; 4x4 fragment per thread.
// Online softmax matches reference semantics exactly:
//   s = valid ? qk*scale : -1e6  (so valid_len==0 -> uniform softmax)
// ---------------------------------------------------------------------------
#define SMEM_FA_BYTES (4 * 64 * 65 * (int)sizeof(float))

__global__ __launch_bounds__(256) void flash_attn(const float* __restrict__ Q,
                                                  const float* __restrict__ K,
                                                  const float* __restrict__ V,
                                                  const int* __restrict__ vlens,
                                                  float* __restrict__ O)
{
    extern __shared__ float sm[];
    float (*Qs)[65] = (float (*)[65])(sm);
    float (*Ks)[65] = (float (*)[65])(sm + 64 * 65);
    float (*Vs)[65] = (float (*)[65])(sm + 2 * 64 * 65);
    float (*Ps)[65] = (float (*)[65])(sm + 3 * 64 * 65);

    const int tid = threadIdx.x;
    const int qt  = blockIdx.x;
    const int h   = blockIdx.y;
    const int b   = blockIdx.z;
    const int head = b * HH + h;

    const float* Qb = Q + ((size_t)head * SS + qt * 64) * DHH;
    const float* Kb = K + (size_t)head * SS * DHH;
    const float* Vb = V + (size_t)head * SS * DHH;
    const int   vlen  = vlens[b];
    const float scale = 0.125f;  // 1/sqrt(64)

    // Load Q tile [64][64]
#pragma unroll
    for (int it = 0; it < 4; it++) {
        int idx = tid + it * 256;     // 0..1023 float4 units
        int row = idx >> 4;
        int c   = (idx & 15) << 2;
        float4 v = *(const float4*)(Qb + (size_t)row * DHH + c);
        Qs[row][c + 0] = v.x; Qs[row][c + 1] = v.y;
        Qs[row][c + 2] = v.z; Qs[row][c + 3] = v.w;
    }

    const int tm = (tid >> 4) << 2;   // q-row base (0..60)
    const int tn = (tid & 15) << 2;   // k-col / d-col base (0..60)

    float m[4], l[4], acc[4][4];
#pragma unroll
    for (int i = 0; i < 4; i++) {
        m[i] = -1e30f;
        l[i] = 0.0f;
#pragma unroll
        for (int j = 0; j < 4; j++) acc[i][j] = 0.0f;
    }

    for (int kb = 0; kb < SS; kb += 64) {
        // Load K,V blocks [64][64]
#pragma unroll
        for (int it = 0; it < 4; it++) {
            int idx = tid + it * 256;
            int row = idx >> 4;
            int c   = (idx & 15) << 2;
            float4 vk = *(const float4*)(Kb + (size_t)(kb + row) * DHH + c);
            Ks[row][c + 0] = vk.x; Ks[row][c + 1] = vk.y;
            Ks[row][c + 2] = vk.z; Ks[row][c + 3] = vk.w;
            float4 vv = *(const float4*)(Vb + (size_t)(kb + row) * DHH + c);
            Vs[row][c + 0] = vv.x; Vs[row][c + 1] = vv.y;
            Vs[row][c + 2] = vv.z; Vs[row][c + 3] = vv.w;
        }
        __syncthreads();

        // Scores: s[i][j] = Q[tm+i] . K[tn+j]
        float s[4][4];
#pragma unroll
        for (int i = 0; i < 4; i++)
#pragma unroll
            for (int j = 0; j < 4; j++) s[i][j] = 0.0f;

#pragma unroll 16
        for (int kk = 0; kk < 64; kk++) {
            float qa[4], kv[4];
#pragma unroll
            for (int i = 0; i < 4; i++) qa[i] = Qs[tm + i][kk];
#pragma unroll
            for (int j = 0; j < 4; j++) kv[j] = Ks[tn + j][kk];
#pragma unroll
            for (int i = 0; i < 4; i++)
#pragma unroll
                for (int j = 0; j < 4; j++)
                    s[i][j] = fmaf(qa[i], kv[j], s[i][j]);
        }

        // scale + key mask (exactly as reference: masked -> -1e6, unscaled)
#pragma unroll
        for (int j = 0; j < 4; j++) {
            bool valid = (kb + tn + j) < vlen;
#pragma unroll
            for (int i = 0; i < 4; i++)
                s[i][j] = valid ? s[i][j] * scale : MASKV;
        }

        // Online softmax update per q-row
#pragma unroll
        for (int i = 0; i < 4; i++) {
            float mx = fmaxf(fmaxf(s[i][0], s[i][1]), fmaxf(s[i][2], s[i][3]));
            mx = fmaxf(mx, __shfl_xor_sync(0xffffffffu, mx, 1));
            mx = fmaxf(mx, __shfl_xor_sync(0xffffffffu, mx, 2));
            mx = fmaxf(mx, __shfl_xor_sync(0xffffffffu, mx, 4));
            mx = fmaxf(mx, __shfl_xor_sync(0xffffffffu, mx, 8));

            float mn   = fmaxf(m[i], mx);
            float corr = __expf(m[i] - mn);
            float rs   = 0.0f;
#pragma unroll
            for (int j = 0; j < 4; j++) {
                float p = __expf(s[i][j] - mn);
                s[i][j] = p;
                rs += p;
            }
            rs += __shfl_xor_sync(0xffffffffu, rs, 1);
            rs += __shfl_xor_sync(0xffffffffu, rs, 2);
            rs += __shfl_xor_sync(0xffffffffu, rs, 4);
            rs += __shfl_xor_sync(0xffffffffu, rs, 8);

            l[i] = l[i] * corr + rs;
            m[i] = mn;
#pragma unroll
            for (int j = 0; j < 4; j++) acc[i][j] *= corr;
#pragma unroll
            for (int j = 0; j < 4; j++) Ps[tm + i][tn + j] = s[i][j];
        }
        __syncthreads();

        // acc += P @ V  (P: [64 q][64 k], V: [64 k][64 d])
#pragma unroll 16
        for (int kk = 0; kk < 64; kk++) {
            float pv[4], vv[4];
#pragma unroll
            for (int i = 0; i < 4; i++) pv[i] = Ps[tm + i][kk];
#pragma unroll
            for (int j = 0; j < 4; j++) vv[j] = Vs[kk][tn + j];
#pragma unroll
            for (int i = 0; i < 4; i++)
#pragma unroll
                for (int j = 0; j < 4; j++)
                    acc[i][j] = fmaf(pv[i], vv[j], acc[i][j]);
        }
        __syncthreads();
    }

    // Normalize and write concat-head layout [B,S,D]
#pragma unroll
    for (int i = 0; i < 4; i++) {
        float inv = 1.0f / l[i];
        size_t row = (size_t)b * SS + qt * 64 + tm + i;
#pragma unroll
        for (int j = 0; j < 4; j++)
            O[row * DD + h * DHH + tn + j] = acc[i][j] * inv;
    }
}

// ---------------------------------------------------------------------------
// Launch
// Inputs (metadata order): key, query, value, valid_lens, Wk, Wq, Wv, Wo
// ---------------------------------------------------------------------------
extern "C" void kernel_launch(void* const* d_in, const int* in_sizes, int n_in,
                              void* d_out, int out_size)
{
    const float* key_   = (const float*)d_in[0];
    const float* query_ = (const float*)d_in[1];
    const float* value_ = (const float*)d_in[2];
    const int*   vlens  = (const int*)  d_in[3];
    const float* Wk     = (const float*)d_in[4];
    const float* Wq     = (const float*)d_in[5];
    const float* Wv     = (const float*)d_in[6];
    const float* Wo     = (const float*)d_in[7];
    float* out = (float*)d_out;

    float *qh, *kh, *vh, *oc;
    cudaGetSymbolAddress((void**)&qh, g_Qh);
    cudaGetSymbolAddress((void**)&kh, g_Kh);
    cudaGetSymbolAddress((void**)&vh, g_Vh);
    cudaGetSymbolAddress((void**)&oc, g_Oc);

    cudaFuncSetAttribute(flash_attn, cudaFuncAttributeMaxDynamicSharedMemorySize,
                         SMEM_FA_BYTES);

    dim3 gg(DD / 128, MM / 128);  // (8, 64)
    gemm_nt<<<gg, 256>>>(query_, Wq, qh, 0);
    gemm_nt<<<gg, 256>>>(key_,   Wk, kh, 0);
    gemm_nt<<<gg, 256>>>(value_, Wv, vh, 0);

    dim3 ga(SS / 64, HH, BB);     // (32, 16, 4)
    flash_attn<<<ga, 256, SMEM_FA_BYTES>>>(qh, kh, vh, vlens, oc);

    gemm_nt<<<gg, 256>>>(oc, Wo, out, 1);
}

// round 6
// speedup vs baseline: 2.2237x; 2.2237x over previous
#include <cuda_runtime.h>
#include <math.h>
#include <stdint.h>

// Problem constants
#define BB   4
#define SS   2048
#define DD   1024
#define HH   16
#define DHH  64
#define MM   (BB * SS)          // 8192 rows
#define MASKV (-1000000.0f)

// Scratch (device globals: allocation-free rule)
__device__ float g_Qh[(size_t)MM * DD];  // [B,H,S,DH] head-split
__device__ float g_Kh[(size_t)MM * DD];
__device__ float g_Vh[(size_t)MM * DD];
__device__ float g_Oc[(size_t)MM * DD];  // [B,S,D] concat-head attention output

// ---------------------------------------------------------------------------
// TF32 helpers
// ---------------------------------------------------------------------------
__device__ __forceinline__ unsigned f2tf(float x) {
    unsigned u;
    asm("cvt.rna.tf32.f32 %0, %1;" : "=r"(u) : "f"(x));   // round-to-nearest (unbiased)
    return u;
}

// D(16x8) += A(16x8) * B(8x8), tf32 in, fp32 accum
__device__ __forceinline__ void mma8(float* d, const unsigned* a, const unsigned* b) {
    asm volatile(
        "mma.sync.aligned.m16n8k8.row.col.f32.tf32.tf32.f32 "
        "{%0,%1,%2,%3}, {%4,%5,%6,%7}, {%8,%9}, {%0,%1,%2,%3};"
        : "+f"(d[0]), "+f"(d[1]), "+f"(d[2]), "+f"(d[3])
        : "r"(a[0]), "r"(a[1]), "r"(a[2]), "r"(a[3]), "r"(b[0]), "r"(b[1]));
}

// ---------------------------------------------------------------------------
// TF32 NT GEMM: C[m,n] = sum_k A[m,k] * W[n,k]
// 128x128 tile, BK=32, 256 threads (8 warps, warp tile 32x64).
// mode 0: write head-split [B,H,S,DH]; mode 1: row-major [M,1024]
// smem stride 36 -> bank = (4*row + col) % 32 -> conflict-free frag loads.
// ---------------------------------------------------------------------------
#define GBK 32
__global__ __launch_bounds__(256) void gemm_tf32(const float* __restrict__ A,
                                                 const float* __restrict__ W,
                                                 float* __restrict__ C,
                                                 int mode)
{
    __shared__ unsigned As[128][GBK + 4];
    __shared__ unsigned Bs[128][GBK + 4];

    const int tid  = threadIdx.x;
    const int lane = tid & 31, warp = tid >> 5;
    const int bm = blockIdx.y * 128, bn = blockIdx.x * 128;
    const int wm = (warp >> 1) * 32, wn = (warp & 1) * 64;
    const int g = lane >> 2, t = lane & 3;

    float acc[2][8][4];
#pragma unroll
    for (int mi = 0; mi < 2; mi++)
#pragma unroll
        for (int nj = 0; nj < 8; nj++)
#pragma unroll
            for (int r = 0; r < 4; r++) acc[mi][nj][r] = 0.0f;

    for (int kt = 0; kt < DD; kt += GBK) {
        // Load 128x32 A and W tiles, converting to tf32
#pragma unroll
        for (int it = 0; it < 4; it++) {
            int idx = tid + it * 256;       // 0..1023 float4 units
            int row = idx >> 3;             // 0..127
            int kc  = (idx & 7) << 2;       // 0..28
            float4 va = *(const float4*)(A + (size_t)(bm + row) * DD + kt + kc);
            As[row][kc + 0] = f2tf(va.x); As[row][kc + 1] = f2tf(va.y);
            As[row][kc + 2] = f2tf(va.z); As[row][kc + 3] = f2tf(va.w);
            float4 vb = *(const float4*)(W + (size_t)(bn + row) * DD + kt + kc);
            Bs[row][kc + 0] = f2tf(vb.x); Bs[row][kc + 1] = f2tf(vb.y);
            Bs[row][kc + 2] = f2tf(vb.z); Bs[row][kc + 3] = f2tf(vb.w);
        }
        __syncthreads();

#pragma unroll
        for (int ks = 0; ks < GBK; ks += 8) {
            unsigned a[2][4], b[8][2];
#pragma unroll
            for (int mi = 0; mi < 2; mi++) {
                int r = wm + mi * 16;
                a[mi][0] = As[r + g][ks + t];
                a[mi][1] = As[r + g + 8][ks + t];
                a[mi][2] = As[r + g][ks + t + 4];
                a[mi][3] = As[r + g + 8][ks + t + 4];
            }
#pragma unroll
            for (int nj = 0; nj < 8; nj++) {
                int c = wn + nj * 8;
                b[nj][0] = Bs[c + g][ks + t];
                b[nj][1] = Bs[c + g][ks + t + 4];
            }
#pragma unroll
            for (int mi = 0; mi < 2; mi++)
#pragma unroll
                for (int nj = 0; nj < 8; nj++)
                    mma8(acc[mi][nj], a[mi], b[nj]);
        }
        __syncthreads();
    }

    if (mode == 0) {
        // head-split epilogue: (m,n) -> [b, h, s, dh]
#pragma unroll
        for (int mi = 0; mi < 2; mi++)
#pragma unroll
            for (int rr = 0; rr < 2; rr++) {
                int m  = bm + wm + mi * 16 + g + rr * 8;
                int b_ = m >> 11;
                int s_ = m & (SS - 1);
#pragma unroll
                for (int nj = 0; nj < 8; nj++) {
                    int n  = bn + wn + nj * 8 + 2 * t;
                    int h_ = n >> 6;
                    int dh = n & 63;
                    float2 v = make_float2(acc[mi][nj][rr * 2], acc[mi][nj][rr * 2 + 1]);
                    *(float2*)&C[(((size_t)b_ * HH + h_) * SS + s_) * DHH + dh] = v;
                }
            }
    } else {
#pragma unroll
        for (int mi = 0; mi < 2; mi++)
#pragma unroll
            for (int rr = 0; rr < 2; rr++) {
                int m = bm + wm + mi * 16 + g + rr * 8;
#pragma unroll
                for (int nj = 0; nj < 8; nj++) {
                    int n = bn + wn + nj * 8 + 2 * t;
                    float2 v = make_float2(acc[mi][nj][rr * 2], acc[mi][nj][rr * 2 + 1]);
                    *(float2*)&C[(size_t)m * DD + n] = v;
                }
            }
    }
}

// ---------------------------------------------------------------------------
// TF32 flash attention. Block = (b, h, 128-row Q tile), 256 threads (8 warps).
// Each warp owns 16 query rows end-to-end (softmax stats stay in-warp).
// K/V blocks of 64 keys. P round-trips via warp-private smem (tf32).
// smem stride 68 -> bank = (4*row + col) % 32 -> conflict-free frag loads.
// ---------------------------------------------------------------------------
#define FSTR 68
#define FA_SMEM_BYTES ((128 + 64 + 64 + 128) * FSTR * 4)   // 104448 B

__global__ __launch_bounds__(256) void flash_tf32(const float* __restrict__ Q,
                                                  const float* __restrict__ K,
                                                  const float* __restrict__ V,
                                                  const int* __restrict__ vlens,
                                                  float* __restrict__ O)
{
    extern __shared__ unsigned sm[];
    unsigned (*Qs)[FSTR] = (unsigned (*)[FSTR])(sm);
    unsigned (*Ks)[FSTR] = (unsigned (*)[FSTR])(sm + 128 * FSTR);
    unsigned (*Vs)[FSTR] = (unsigned (*)[FSTR])(sm + 192 * FSTR);
    unsigned (*Ps)[FSTR] = (unsigned (*)[FSTR])(sm + 256 * FSTR);

    const int tid  = threadIdx.x;
    const int lane = tid & 31, warp = tid >> 5;
    const int qt = blockIdx.x, h = blockIdx.y, b = blockIdx.z;
    const int head = b * HH + h;

    const float* Qb = Q + ((size_t)head * SS + qt * 128) * DHH;
    const float* Kb = K + (size_t)head * SS * DHH;
    const float* Vb = V + (size_t)head * SS * DHH;
    const int   vlen = vlens[b];
    const int   g = lane >> 2, t = lane & 3;
    const int   wrow = warp * 16;
    const float scale = 0.125f;   // 1/sqrt(64)

    // Load Q tile [128][64] as tf32
#pragma unroll
    for (int it = 0; it < 8; it++) {
        int idx = tid + it * 256;      // 0..2047 float4 units
        int row = idx >> 4;
        int c   = (idx & 15) << 2;
        float4 v = *(const float4*)(Qb + (size_t)row * DHH + c);
        Qs[row][c + 0] = f2tf(v.x); Qs[row][c + 1] = f2tf(v.y);
        Qs[row][c + 2] = f2tf(v.z); Qs[row][c + 3] = f2tf(v.w);
    }

    float o[8][4];
#pragma unroll
    for (int nj = 0; nj < 8; nj++)
#pragma unroll
        for (int r = 0; r < 4; r++) o[nj][r] = 0.0f;
    float m0 = -1e30f, m1 = -1e30f, l0 = 0.0f, l1 = 0.0f;

    for (int kb = 0; kb < SS; kb += 64) {
        __syncthreads();   // protect Ks/Vs (and Ps cross-iter) from prior reads
#pragma unroll
        for (int it = 0; it < 4; it++) {
            int idx = tid + it * 256;      // 0..1023 float4 units
            int row = idx >> 4;
            int c   = (idx & 15) << 2;
            float4 vk = *(const float4*)(Kb + (size_t)(kb + row) * DHH + c);
            Ks[row][c + 0] = f2tf(vk.x); Ks[row][c + 1] = f2tf(vk.y);
            Ks[row][c + 2] = f2tf(vk.z); Ks[row][c + 3] = f2tf(vk.w);
            float4 vv = *(const float4*)(Vb + (size_t)(kb + row) * DHH + c);
            Vs[row][c + 0] = f2tf(vv.x); Vs[row][c + 1] = f2tf(vv.y);
            Vs[row][c + 2] = f2tf(vv.z); Vs[row][c + 3] = f2tf(vv.w);
        }
        __syncthreads();

        // S = Q @ K^T  (warp: 16 rows x 64 keys = 8 n-tiles)
        float s[8][4];
#pragma unroll
        for (int nj = 0; nj < 8; nj++)
#pragma unroll
            for (int r = 0; r < 4; r++) s[nj][r] = 0.0f;

#pragma unroll
        for (int ks = 0; ks < DHH; ks += 8) {
            unsigned a[4];
            a[0] = Qs[wrow + g][ks + t];
            a[1] = Qs[wrow + g + 8][ks + t];
            a[2] = Qs[wrow + g][ks + t + 4];
            a[3] = Qs[wrow + g + 8][ks + t + 4];
#pragma unroll
            for (int nj = 0; nj < 8; nj++) {
                unsigned bf[2];
                bf[0] = Ks[nj * 8 + g][ks + t];
                bf[1] = Ks[nj * 8 + g][ks + t + 4];
                mma8(s[nj], a, bf);
            }
        }

        // scale + mask (reference semantics: masked -> -1e6, unscaled)
        float rmax0 = -1e30f, rmax1 = -1e30f;
#pragma unroll
        for (int nj = 0; nj < 8; nj++) {
            int c0 = kb + nj * 8 + 2 * t;
            bool v0 = c0 < vlen, v1 = (c0 + 1) < vlen;
            s[nj][0] = v0 ? s[nj][0] * scale : MASKV;
            s[nj][1] = v1 ? s[nj][1] * scale : MASKV;
            s[nj][2] = v0 ? s[nj][2] * scale : MASKV;
            s[nj][3] = v1 ? s[nj][3] * scale : MASKV;
            rmax0 = fmaxf(rmax0, fmaxf(s[nj][0], s[nj][1]));
            rmax1 = fmaxf(rmax1, fmaxf(s[nj][2], s[nj][3]));
        }
        rmax0 = fmaxf(rmax0, __shfl_xor_sync(0xffffffffu, rmax0, 1));
        rmax0 = fmaxf(rmax0, __shfl_xor_sync(0xffffffffu, rmax0, 2));
        rmax1 = fmaxf(rmax1, __shfl_xor_sync(0xffffffffu, rmax1, 1));
        rmax1 = fmaxf(rmax1, __shfl_xor_sync(0xffffffffu, rmax1, 2));

        float mn0 = fmaxf(m0, rmax0), mn1 = fmaxf(m1, rmax1);
        float corr0 = __expf(m0 - mn0), corr1 = __expf(m1 - mn1);
        float rs0 = 0.0f, rs1 = 0.0f;

#pragma unroll
        for (int nj = 0; nj < 8; nj++) {
            float p0 = __expf(s[nj][0] - mn0);
            float p1 = __expf(s[nj][1] - mn0);
            float p2 = __expf(s[nj][2] - mn1);
            float p3 = __expf(s[nj][3] - mn1);
            rs0 += p0 + p1;
            rs1 += p2 + p3;
            *(uint2*)&Ps[wrow + g][nj * 8 + 2 * t]     = make_uint2(f2tf(p0), f2tf(p1));
            *(uint2*)&Ps[wrow + g + 8][nj * 8 + 2 * t] = make_uint2(f2tf(p2), f2tf(p3));
        }
        rs0 += __shfl_xor_sync(0xffffffffu, rs0, 1);
        rs0 += __shfl_xor_sync(0xffffffffu, rs0, 2);
        rs1 += __shfl_xor_sync(0xffffffffu, rs1, 1);
        rs1 += __shfl_xor_sync(0xffffffffu, rs1, 2);

        l0 = l0 * corr0 + rs0;
        l1 = l1 * corr1 + rs1;
        m0 = mn0; m1 = mn1;
#pragma unroll
        for (int nj = 0; nj < 8; nj++) {
            o[nj][0] *= corr0; o[nj][1] *= corr0;
            o[nj][2] *= corr1; o[nj][3] *= corr1;
        }

        __syncwarp();   // Ps stores visible to this warp's frag loads

        // O += P @ V  (A = P[16 x 64keys] warp-private, B = V[key][d])
#pragma unroll
        for (int ks = 0; ks < 64; ks += 8) {
            unsigned a[4];
            a[0] = Ps[wrow + g][ks + t];
            a[1] = Ps[wrow + g + 8][ks + t];
            a[2] = Ps[wrow + g][ks + t + 4];
            a[3] = Ps[wrow + g + 8][ks + t + 4];
#pragma unroll
            for (int nj = 0; nj < 8; nj++) {
                unsigned bf[2];
                bf[0] = Vs[ks + t][nj * 8 + g];
                bf[1] = Vs[ks + t + 4][nj * 8 + g];
                mma8(o[nj], a, bf);
            }
        }
    }

    // Normalize, write concat-head [B,S,D]
    float inv0 = 1.0f / l0, inv1 = 1.0f / l1;
    int row0 = qt * 128 + wrow + g;
    size_t base0 = ((size_t)b * SS + row0) * DD + h * DHH;
    size_t base1 = base0 + (size_t)8 * DD;
#pragma unroll
    for (int nj = 0; nj < 8; nj++) {
        *(float2*)&O[base0 + nj * 8 + 2 * t] = make_float2(o[nj][0] * inv0, o[nj][1] * inv0);
        *(float2*)&O[base1 + nj * 8 + 2 * t] = make_float2(o[nj][2] * inv1, o[nj][3] * inv1);
    }
}

// ---------------------------------------------------------------------------
// Launch. Inputs (metadata order): key, query, value, valid_lens, Wk, Wq, Wv, Wo
// ---------------------------------------------------------------------------
extern "C" void kernel_launch(void* const* d_in, const int* in_sizes, int n_in,
                              void* d_out, int out_size)
{
    const float* key_   = (const float*)d_in[0];
    const float* query_ = (const float*)d_in[1];
    const float* value_ = (const float*)d_in[2];
    const int*   vlens  = (const int*)  d_in[3];
    const float* Wk     = (const float*)d_in[4];
    const float* Wq     = (const float*)d_in[5];
    const float* Wv     = (const float*)d_in[6];
    const float* Wo     = (const float*)d_in[7];
    float* out = (float*)d_out;

    float *qh, *kh, *vh, *oc;
    cudaGetSymbolAddress((void**)&qh, g_Qh);
    cudaGetSymbolAddress((void**)&kh, g_Kh);
    cudaGetSymbolAddress((void**)&vh, g_Vh);
    cudaGetSymbolAddress((void**)&oc, g_Oc);

    cudaFuncSetAttribute(flash_tf32, cudaFuncAttributeMaxDynamicSharedMemorySize,
                         FA_SMEM_BYTES);

    dim3 gg(DD / 128, MM / 128);  // (8, 64)
    gemm_tf32<<<gg, 256>>>(query_, Wq, qh, 0);
    gemm_tf32<<<gg, 256>>>(key_,   Wk, kh, 0);
    gemm_tf32<<<gg, 256>>>(value_, Wv, vh, 0);

    dim3 ga(SS / 128, HH, BB);    // (16, 16, 4)
    flash_tf32<<<ga, 256, FA_SMEM_BYTES>>>(qh, kh, vh, vlens, oc);

    gemm_tf32<<<gg, 256>>>(oc, Wo, out, 1);
}

// round 9
// speedup vs baseline: 3.2147x; 1.4456x over previous
#include <cuda_runtime.h>
#include <math.h>
#include <stdint.h>

// Problem constants
#define BB   4
#define SS   2048
#define DD   1024
#define HH   16
#define DHH  64
#define MM   (BB * SS)          // 8192 rows
#define MASKV (-1000000.0f)

// Scratch (device globals: allocation-free rule)
__device__ float g_Qh[(size_t)MM * DD];  // [B,H,S,DH] head-split
__device__ float g_Kh[(size_t)MM * DD];
__device__ float g_Vh[(size_t)MM * DD];
__device__ float g_Oc[(size_t)MM * DD];  // [B,S,D] concat-head attention output

// ---------------------------------------------------------------------------
// TF32 helpers
// ---------------------------------------------------------------------------
__device__ __forceinline__ unsigned f2tf(float x) {
    unsigned u;
    asm("cvt.rna.tf32.f32 %0, %1;" : "=r"(u) : "f"(x));   // round-to-nearest (unbiased)
    return u;
}

// D(16x8) += A(16x8) * B(8x8), tf32 in, fp32 accum
__device__ __forceinline__ void mma8(float* d, const unsigned* a, const unsigned* b) {
    asm volatile(
        "mma.sync.aligned.m16n8k8.row.col.f32.tf32.tf32.f32 "
        "{%0,%1,%2,%3}, {%4,%5,%6,%7}, {%8,%9}, {%0,%1,%2,%3};"
        : "+f"(d[0]), "+f"(d[1]), "+f"(d[2]), "+f"(d[3])
        : "r"(a[0]), "r"(a[1]), "r"(a[2]), "r"(a[3]), "r"(b[0]), "r"(b[1]));
}

// ---------------------------------------------------------------------------
// TF32 NT GEMM with software pipelining: C[m,n] = sum_k A[m,k] * W[n,k]
// 128x128 tile, BK=32, 256 threads (8 warps, warp tile 32x64).
// Double-buffered smem (2 stages), register prefetch of tile t+1 during
// compute of tile t, ONE __syncthreads per K-tile. 2 CTAs/SM.
// mode 0: write head-split [B,H,S,DH]; mode 1: row-major [M,1024]
// smem stride 36 -> bank = (4*row + col) % 32 -> conflict-free frag loads.
// ---------------------------------------------------------------------------
#define GBK  32
#define GSTR 36
#define G_STAGE (2 * 128 * GSTR)                       // A + B per stage (units)
#define G_SMEM_BYTES (2 * G_STAGE * (int)sizeof(unsigned))  // 73728 B

__global__ __launch_bounds__(256, 2) void gemm_tf32(const float* __restrict__ A,
                                                    const float* __restrict__ W,
                                                    float* __restrict__ C,
                                                    int mode)
{
    extern __shared__ unsigned gsm[];

    const int tid  = threadIdx.x;
    const int lane = tid & 31, warp = tid >> 5;
    const int bm = blockIdx.y * 128, bn = blockIdx.x * 128;
    const int wm = (warp >> 1) * 32, wn = (warp & 1) * 64;
    const int g = lane >> 2, t = lane & 3;

    float acc[2][8][4];
#pragma unroll
    for (int mi = 0; mi < 2; mi++)
#pragma unroll
        for (int nj = 0; nj < 8; nj++)
#pragma unroll
            for (int r = 0; r < 4; r++) acc[mi][nj][r] = 0.0f;

    // Per-thread load coordinates (4 float4 for A, 4 for B per tile)
    int lr[4], lk[4];
#pragma unroll
    for (int it = 0; it < 4; it++) {
        int idx = tid + it * 256;       // 0..1023
        lr[it] = idx >> 3;              // row 0..127
        lk[it] = (idx & 7) << 2;        // k-col 0,4,...,28
    }

    float4 pa[4], pb[4];

    // Prologue: load tile 0
#pragma unroll
    for (int it = 0; it < 4; it++) {
        pa[it] = *(const float4*)(A + (size_t)(bm + lr[it]) * DD + lk[it]);
        pb[it] = *(const float4*)(W + (size_t)(bn + lr[it]) * DD + lk[it]);
    }
    // Store tile 0 into stage 0
#pragma unroll
    for (int it = 0; it < 4; it++) {
        unsigned* As_ = gsm + 0 * G_STAGE + lr[it] * GSTR + lk[it];
        unsigned* Bs_ = gsm + 0 * G_STAGE + 128 * GSTR + lr[it] * GSTR + lk[it];
        As_[0] = f2tf(pa[it].x); As_[1] = f2tf(pa[it].y);
        As_[2] = f2tf(pa[it].z); As_[3] = f2tf(pa[it].w);
        Bs_[0] = f2tf(pb[it].x); Bs_[1] = f2tf(pb[it].y);
        Bs_[2] = f2tf(pb[it].z); Bs_[3] = f2tf(pb[it].w);
    }
    __syncthreads();

    const int NT = DD / GBK;   // 32 K-tiles
    for (int kt = 0; kt < NT; kt++) {
        const int s = kt & 1;

        // Prefetch next tile's global data (LDG latency hides under MMAs)
        if (kt + 1 < NT) {
            const int k0 = (kt + 1) * GBK;
#pragma unroll
            for (int it = 0; it < 4; it++) {
                pa[it] = *(const float4*)(A + (size_t)(bm + lr[it]) * DD + k0 + lk[it]);
                pb[it] = *(const float4*)(W + (size_t)(bn + lr[it]) * DD + k0 + lk[it]);
            }
        }

        // Compute from stage s
        const unsigned* Asb = gsm + s * G_STAGE;
        const unsigned* Bsb = Asb + 128 * GSTR;
#pragma unroll
        for (int ks = 0; ks < GBK; ks += 8) {
            unsigned a[2][4], b[8][2];
#pragma unroll
            for (int mi = 0; mi < 2; mi++) {
                int r = wm + mi * 16;
                a[mi][0] = Asb[(r + g) * GSTR + ks + t];
                a[mi][1] = Asb[(r + g + 8) * GSTR + ks + t];
                a[mi][2] = Asb[(r + g) * GSTR + ks + t + 4];
                a[mi][3] = Asb[(r + g + 8) * GSTR + ks + t + 4];
            }
#pragma unroll
            for (int nj = 0; nj < 8; nj++) {
                int c = wn + nj * 8;
                b[nj][0] = Bsb[(c + g) * GSTR + ks + t];
                b[nj][1] = Bsb[(c + g) * GSTR + ks + t + 4];
            }
#pragma unroll
            for (int mi = 0; mi < 2; mi++)
#pragma unroll
                for (int nj = 0; nj < 8; nj++)
                    mma8(acc[mi][nj], a[mi], b[nj]);
        }

        // Store prefetched tile into the other stage (safe: that stage's
        // consumers finished at the sync ending iteration kt-1)
        if (kt + 1 < NT) {
            unsigned* Asn = gsm + (s ^ 1) * G_STAGE;
            unsigned* Bsn = Asn + 128 * GSTR;
#pragma unroll
            for (int it = 0; it < 4; it++) {
                unsigned* As_ = Asn + lr[it] * GSTR + lk[it];
                unsigned* Bs_ = Bsn + lr[it] * GSTR + lk[it];
                As_[0] = f2tf(pa[it].x); As_[1] = f2tf(pa[it].y);
                As_[2] = f2tf(pa[it].z); As_[3] = f2tf(pa[it].w);
                Bs_[0] = f2tf(pb[it].x); Bs_[1] = f2tf(pb[it].y);
                Bs_[2] = f2tf(pb[it].z); Bs_[3] = f2tf(pb[it].w);
            }
        }
        __syncthreads();
    }

    if (mode == 0) {
        // head-split epilogue: (m,n) -> [b, h, s, dh]
#pragma unroll
        for (int mi = 0; mi < 2; mi++)
#pragma unroll
            for (int rr = 0; rr < 2; rr++) {
                int m  = bm + wm + mi * 16 + g + rr * 8;
                int b_ = m >> 11;
                int s_ = m & (SS - 1);
#pragma unroll
                for (int nj = 0; nj < 8; nj++) {
                    int n  = bn + wn + nj * 8 + 2 * t;
                    int h_ = n >> 6;
                    int dh = n & 63;
                    float2 v = make_float2(acc[mi][nj][rr * 2], acc[mi][nj][rr * 2 + 1]);
                    *(float2*)&C[(((size_t)b_ * HH + h_) * SS + s_) * DHH + dh] = v;
                }
            }
    } else {
#pragma unroll
        for (int mi = 0; mi < 2; mi++)
#pragma unroll
            for (int rr = 0; rr < 2; rr++) {
                int m = bm + wm + mi * 16 + g + rr * 8;
#pragma unroll
                for (int nj = 0; nj < 8; nj++) {
                    int n = bn + wn + nj * 8 + 2 * t;
                    float2 v = make_float2(acc[mi][nj][rr * 2], acc[mi][nj][rr * 2 + 1]);
                    *(float2*)&C[(size_t)m * DD + n] = v;
                }
            }
    }
}

// ---------------------------------------------------------------------------
// TF32 flash attention (unchanged from R6: 637us, tensor=35.5%).
// Block = (b, h, 128-row Q tile), 256 threads (8 warps).
// ---------------------------------------------------------------------------
#define FSTR 68
#define FA_SMEM_BYTES ((128 + 64 + 64 + 128) * FSTR * 4)   // 104448 B

__global__ __launch_bounds__(256) void flash_tf32(const float* __restrict__ Q,
                                                  const float* __restrict__ K,
                                                  const float* __restrict__ V,
                                                  const int* __restrict__ vlens,
                                                  float* __restrict__ O)
{
    extern __shared__ unsigned sm[];
    unsigned (*Qs)[FSTR] = (unsigned (*)[FSTR])(sm);
    unsigned (*Ks)[FSTR] = (unsigned (*)[FSTR])(sm + 128 * FSTR);
    unsigned (*Vs)[FSTR] = (unsigned (*)[FSTR])(sm + 192 * FSTR);
    unsigned (*Ps)[FSTR] = (unsigned (*)[FSTR])(sm + 256 * FSTR);

    const int tid  = threadIdx.x;
    const int lane = tid & 31, warp = tid >> 5;
    const int qt = blockIdx.x, h = blockIdx.y, b = blockIdx.z;
    const int head = b * HH + h;

    const float* Qb = Q + ((size_t)head * SS + qt * 128) * DHH;
    const float* Kb = K + (size_t)head * SS * DHH;
    const float* Vb = V + (size_t)head * SS * DHH;
    const int   vlen = vlens[b];
    const int   g = lane >> 2, t = lane & 3;
    const int   wrow = warp * 16;
    const float scale = 0.125f;

#pragma unroll
    for (int it = 0; it < 8; it++) {
        int idx = tid + it * 256;
        int row = idx >> 4;
        int c   = (idx & 15) << 2;
        float4 v = *(const float4*)(Qb + (size_t)row * DHH + c);
        Qs[row][c + 0] = f2tf(v.x); Qs[row][c + 1] = f2tf(v.y);
        Qs[row][c + 2] = f2tf(v.z); Qs[row][c + 3] = f2tf(v.w);
    }

    float o[8][4];
#pragma unroll
    for (int nj = 0; nj < 8; nj++)
#pragma unroll
        for (int r = 0; r < 4; r++) o[nj][r] = 0.0f;
    float m0 = -1e30f, m1 = -1e30f, l0 = 0.0f, l1 = 0.0f;

    for (int kb = 0; kb < SS; kb += 64) {
        __syncthreads();
#pragma unroll
        for (int it = 0; it < 4; it++) {
            int idx = tid + it * 256;
            int row = idx >> 4;
            int c   = (idx & 15) << 2;
            float4 vk = *(const float4*)(Kb + (size_t)(kb + row) * DHH + c);
            Ks[row][c + 0] = f2tf(vk.x); Ks[row][c + 1] = f2tf(vk.y);
            Ks[row][c + 2] = f2tf(vk.z); Ks[row][c + 3] = f2tf(vk.w);
            float4 vv = *(const float4*)(Vb + (size_t)(kb + row) * DHH + c);
            Vs[row][c + 0] = f2tf(vv.x); Vs[row][c + 1] = f2tf(vv.y);
            Vs[row][c + 2] = f2tf(vv.z); Vs[row][c + 3] = f2tf(vv.w);
        }
        __syncthreads();

        float s[8][4];
#pragma unroll
        for (int nj = 0; nj < 8; nj++)
#pragma unroll
            for (int r = 0; r < 4; r++) s[nj][r] = 0.0f;

#pragma unroll
        for (int ks = 0; ks < DHH; ks += 8) {
            unsigned a[4];
            a[0] = Qs[wrow + g][ks + t];
            a[1] = Qs[wrow + g + 8][ks + t];
            a[2] = Qs[wrow + g][ks + t + 4];
            a[3] = Qs[wrow + g + 8][ks + t + 4];
#pragma unroll
            for (int nj = 0; nj < 8; nj++) {
                unsigned bf[2];
                bf[0] = Ks[nj * 8 + g][ks + t];
                bf[1] = Ks[nj * 8 + g][ks + t + 4];
                mma8(s[nj], a, bf);
            }
        }

        float rmax0 = -1e30f, rmax1 = -1e30f;
#pragma unroll
        for (int nj = 0; nj < 8; nj++) {
            int c0 = kb + nj * 8 + 2 * t;
            bool v0 = c0 < vlen, v1 = (c0 + 1) < vlen;
            s[nj][0] = v0 ? s[nj][0] * scale : MASKV;
            s[nj][1] = v1 ? s[nj][1] * scale : MASKV;
            s[nj][2] = v0 ? s[nj][2] * scale : MASKV;
            s[nj][3] = v1 ? s[nj][3] * scale : MASKV;
            rmax0 = fmaxf(rmax0, fmaxf(s[nj][0], s[nj][1]));
            rmax1 = fmaxf(rmax1, fmaxf(s[nj][2], s[nj][3]));
        }
        rmax0 = fmaxf(rmax0, __shfl_xor_sync(0xffffffffu, rmax0, 1));
        rmax0 = fmaxf(rmax0, __shfl_xor_sync(0xffffffffu, rmax0, 2));
        rmax1 = fmaxf(rmax1, __shfl_xor_sync(0xffffffffu, rmax1, 1));
        rmax1 = fmaxf(rmax1, __shfl_xor_sync(0xffffffffu, rmax1, 2));

        float mn0 = fmaxf(m0, rmax0), mn1 = fmaxf(m1, rmax1);
        float corr0 = __expf(m0 - mn0), corr1 = __expf(m1 - mn1);
        float rs0 = 0.0f, rs1 = 0.0f;

#pragma unroll
        for (int nj = 0; nj < 8; nj++) {
            float p0 = __expf(s[nj][0] - mn0);
            float p1 = __expf(s[nj][1] - mn0);
            float p2 = __expf(s[nj][2] - mn1);
            float p3 = __expf(s[nj][3] - mn1);
            rs0 += p0 + p1;
            rs1 += p2 + p3;
            *(uint2*)&Ps[wrow + g][nj * 8 + 2 * t]     = make_uint2(f2tf(p0), f2tf(p1));
            *(uint2*)&Ps[wrow + g + 8][nj * 8 + 2 * t] = make_uint2(f2tf(p2), f2tf(p3));
        }
        rs0 += __shfl_xor_sync(0xffffffffu, rs0, 1);
        rs0 += __shfl_xor_sync(0xffffffffu, rs0, 2);
        rs1 += __shfl_xor_sync(0xffffffffu, rs1, 1);
        rs1 += __shfl_xor_sync(0xffffffffu, rs1, 2);

        l0 = l0 * corr0 + rs0;
        l1 = l1 * corr1 + rs1;
        m0 = mn0; m1 = mn1;
#pragma unroll
        for (int nj = 0; nj < 8; nj++) {
            o[nj][0] *= corr0; o[nj][1] *= corr0;
            o[nj][2] *= corr1; o[nj][3] *= corr1;
        }

        __syncwarp();

#pragma unroll
        for (int ks = 0; ks < 64; ks += 8) {
            unsigned a[4];
            a[0] = Ps[wrow + g][ks + t];
            a[1] = Ps[wrow + g + 8][ks + t];
            a[2] = Ps[wrow + g][ks + t + 4];
            a[3] = Ps[wrow + g + 8][ks + t + 4];
#pragma unroll
            for (int nj = 0; nj < 8; nj++) {
                unsigned bf[2];
                bf[0] = Vs[ks + t][nj * 8 + g];
                bf[1] = Vs[ks + t + 4][nj * 8 + g];
                mma8(o[nj], a, bf);
            }
        }
    }

    float inv0 = 1.0f / l0, inv1 = 1.0f / l1;
    int row0 = qt * 128 + wrow + g;
    size_t base0 = ((size_t)b * SS + row0) * DD + h * DHH;
    size_t base1 = base0 + (size_t)8 * DD;
#pragma unroll
    for (int nj = 0; nj < 8; nj++) {
        *(float2*)&O[base0 + nj * 8 + 2 * t] = make_float2(o[nj][0] * inv0, o[nj][1] * inv0);
        *(float2*)&O[base1 + nj * 8 + 2 * t] = make_float2(o[nj][2] * inv1, o[nj][3] * inv1);
    }
}

// ---------------------------------------------------------------------------
// Launch. Inputs (metadata order): key, query, value, valid_lens, Wk, Wq, Wv, Wo
// ---------------------------------------------------------------------------
extern "C" void kernel_launch(void* const* d_in, const int* in_sizes, int n_in,
                              void* d_out, int out_size)
{
    const float* key_   = (const float*)d_in[0];
    const float* query_ = (const float*)d_in[1];
    const float* value_ = (const float*)d_in[2];
    const int*   vlens  = (const int*)  d_in[3];
    const float* Wk     = (const float*)d_in[4];
    const float* Wq     = (const float*)d_in[5];
    const float* Wv     = (const float*)d_in[6];
    const float* Wo     = (const float*)d_in[7];
    float* out = (float*)d_out;

    float *qh, *kh, *vh, *oc;
    cudaGetSymbolAddress((void**)&qh, g_Qh);
    cudaGetSymbolAddress((void**)&kh, g_Kh);
    cudaGetSymbolAddress((void**)&vh, g_Vh);
    cudaGetSymbolAddress((void**)&oc, g_Oc);

    cudaFuncSetAttribute(gemm_tf32, cudaFuncAttributeMaxDynamicSharedMemorySize,
                         G_SMEM_BYTES);
    cudaFuncSetAttribute(flash_tf32, cudaFuncAttributeMaxDynamicSharedMemorySize,
                         FA_SMEM_BYTES);

    dim3 gg(DD / 128, MM / 128);  // (8, 64)
    gemm_tf32<<<gg, 256, G_SMEM_BYTES>>>(query_, Wq, qh, 0);
    gemm_tf32<<<gg, 256, G_SMEM_BYTES>>>(key_,   Wk, kh, 0);
    gemm_tf32<<<gg, 256, G_SMEM_BYTES>>>(value_, Wv, vh, 0);

    dim3 ga(SS / 128, HH, BB);    // (16, 16, 4)
    flash_tf32<<<ga, 256, FA_SMEM_BYTES>>>(qh, kh, vh, vlens, oc);

    gemm_tf32<<<gg, 256, G_SMEM_BYTES>>>(oc, Wo, out, 1);
}

// round 11
// speedup vs baseline: 3.2771x; 1.0194x over previous
#include <cuda_runtime.h>
#include <math.h>
#include <stdint.h>

// Problem constants
#define BB   4
#define SS   2048
#define DD   1024
#define HH   16
#define DHH  64
#define MM   (BB * SS)          // 8192 rows
#define MASKV (-1000000.0f)

// Scratch (device globals: allocation-free rule)
__device__ float g_Qh[(size_t)MM * DD];  // [B,H,S,DH] head-split
__device__ float g_Kh[(size_t)MM * DD];
__device__ float g_Vh[(size_t)MM * DD];
__device__ float g_Oc[(size_t)MM * DD];  // [B,S,D] concat-head attention output

// ---------------------------------------------------------------------------
// Helpers
// ---------------------------------------------------------------------------
__device__ __forceinline__ uint32_t smem_u32(const void* p) {
    uint32_t a;
    asm("{ .reg .u64 t; cvta.to.shared.u64 t, %1; cvt.u32.u64 %0, t; }" : "=r"(a) : "l"(p));
    return a;
}
__device__ __forceinline__ unsigned f2tf(float x) {
    unsigned u;
    asm("cvt.rna.tf32.f32 %0, %1;" : "=r"(u) : "f"(x));
    return u;
}
__device__ __forceinline__ void mma8(float* d, const unsigned* a, const unsigned* b) {
    asm volatile(
        "mma.sync.aligned.m16n8k8.row.col.f32.tf32.tf32.f32 "
        "{%0,%1,%2,%3}, {%4,%5,%6,%7}, {%8,%9}, {%0,%1,%2,%3};"
        : "+f"(d[0]), "+f"(d[1]), "+f"(d[2]), "+f"(d[3])
        : "r"(a[0]), "r"(a[1]), "r"(a[2]), "r"(a[3]), "r"(b[0]), "r"(b[1]));
}
__device__ __forceinline__ void cpa16(uint32_t dst, const float* src) {
    asm volatile("cp.async.cg.shared.global [%0], [%1], 16;" :: "r"(dst), "l"(src));
}
#define CPA_COMMIT() asm volatile("cp.async.commit_group;" ::: "memory")
#define CPA_WAIT1()  asm volatile("cp.async.wait_group 1;" ::: "memory")
#define CPA_WAIT0()  asm volatile("cp.async.wait_group 0;" ::: "memory")

// ---------------------------------------------------------------------------
// TF32 NT GEMM, 3-stage cp.async pipeline: C[m,n] = sum_k A[m,k] * W[n,k]
// 128x128 tile, BK=32, 256 threads (8 warps, warp tile 32x64), 2 CTAs/SM.
// Raw fp32 smem stages; f2tf on the consume side. ONE __syncthreads/K-tile.
// mode 0: head-split [B,H,S,DH]; mode 1: row-major [M,1024]
// ---------------------------------------------------------------------------
struct GArgs { const float* A[3]; const float* W[3]; float* C[3]; int mode; };

#define GBK  32
#define GSTR 36
#define G_STAGE_W (2 * 128 * GSTR)                  // 9216 words per stage
#define G_SMEM_BYTES (3 * G_STAGE_W * 4)            // 110592 B

__global__ __launch_bounds__(256, 2) void gemm_cp(GArgs args)
{
    extern __shared__ float gsm[];
    const uint32_t sb = smem_u32(gsm);
    const int tid  = threadIdx.x;
    const int lane = tid & 31, warp = tid >> 5;
    const int z  = blockIdx.z;
    const float* __restrict__ A = args.A[z];
    const float* __restrict__ W = args.W[z];
    float* __restrict__ C = args.C[z];
    const int mode = args.mode;
    const int bm = blockIdx.y * 128, bn = blockIdx.x * 128;
    const int wm = (warp >> 1) * 32, wn = (warp & 1) * 64;
    const int g = lane >> 2, t = lane & 3;

    // Per-thread staging coords: 4 16B chunks of A + 4 of B per tile
    int ar[4], ac[4];
#pragma unroll
    for (int i = 0; i < 4; i++) {
        int idx = tid + i * 256;        // 0..1023
        ar[i] = idx >> 3;               // row 0..127
        ac[i] = (idx & 7) << 2;         // k-col 0,4..28
    }

#define G_ISSUE(ktile, stg) do {                                               \
    uint32_t base_ = sb + (uint32_t)(stg) * (G_STAGE_W * 4);                   \
    const float* As_ = A + (size_t)bm * DD + (ktile) * GBK;                    \
    const float* Ws_ = W + (size_t)bn * DD + (ktile) * GBK;                    \
    _Pragma("unroll")                                                          \
    for (int i_ = 0; i_ < 4; i_++) {                                           \
        cpa16(base_ + (uint32_t)((ar[i_] * GSTR + ac[i_]) * 4),                \
              As_ + (size_t)ar[i_] * DD + ac[i_]);                             \
        cpa16(base_ + (uint32_t)((128 * GSTR + ar[i_] * GSTR + ac[i_]) * 4),   \
              Ws_ + (size_t)ar[i_] * DD + ac[i_]);                             \
    }                                                                          \
    CPA_COMMIT();                                                              \
} while (0)

    float acc[2][8][4];
#pragma unroll
    for (int mi = 0; mi < 2; mi++)
#pragma unroll
        for (int nj = 0; nj < 8; nj++)
#pragma unroll
            for (int r = 0; r < 4; r++) acc[mi][nj][r] = 0.0f;

    G_ISSUE(0, 0);
    G_ISSUE(1, 1);

    const int NT = DD / GBK;   // 32
    for (int kt = 0; kt < NT; kt++) {
        if (kt < NT - 1) { CPA_WAIT1(); } else { CPA_WAIT0(); }
        __syncthreads();
        if (kt + 2 < NT) G_ISSUE(kt + 2, (kt + 2) % 3);

        const float* Ast = gsm + (kt % 3) * G_STAGE_W;
        const float* Bst = Ast + 128 * GSTR;
#pragma unroll
        for (int ks = 0; ks < GBK; ks += 8) {
            unsigned a[2][4], b[8][2];
#pragma unroll
            for (int mi = 0; mi < 2; mi++) {
                int r0 = (wm + mi * 16 + g) * GSTR;
                int r8 = (wm + mi * 16 + g + 8) * GSTR;
                a[mi][0] = f2tf(Ast[r0 + ks + t]);
                a[mi][1] = f2tf(Ast[r8 + ks + t]);
                a[mi][2] = f2tf(Ast[r0 + ks + t + 4]);
                a[mi][3] = f2tf(Ast[r8 + ks + t + 4]);
            }
#pragma unroll
            for (int nj = 0; nj < 8; nj++) {
                int c0 = (wn + nj * 8 + g) * GSTR;
                b[nj][0] = f2tf(Bst[c0 + ks + t]);
                b[nj][1] = f2tf(Bst[c0 + ks + t + 4]);
            }
#pragma unroll
            for (int mi = 0; mi < 2; mi++)
#pragma unroll
                for (int nj = 0; nj < 8; nj++)
                    mma8(acc[mi][nj], a[mi], b[nj]);
        }
    }
#undef G_ISSUE

    if (mode == 0) {
#pragma unroll
        for (int mi = 0; mi < 2; mi++)
#pragma unroll
            for (int rr = 0; rr < 2; rr++) {
                int m  = bm + wm + mi * 16 + g + rr * 8;
                int b_ = m >> 11;
                int s_ = m & (SS - 1);
#pragma unroll
                for (int nj = 0; nj < 8; nj++) {
                    int n  = bn + wn + nj * 8 + 2 * t;
                    int h_ = n >> 6;
                    int dh = n & 63;
                    float2 v = make_float2(acc[mi][nj][rr * 2], acc[mi][nj][rr * 2 + 1]);
                    *(float2*)&C[(((size_t)b_ * HH + h_) * SS + s_) * DHH + dh] = v;
                }
            }
    } else {
#pragma unroll
        for (int mi = 0; mi < 2; mi++)
#pragma unroll
            for (int rr = 0; rr < 2; rr++) {
                int m = bm + wm + mi * 16 + g + rr * 8;
#pragma unroll
                for (int nj = 0; nj < 8; nj++) {
                    int n = bn + wn + nj * 8 + 2 * t;
                    float2 v = make_float2(acc[mi][nj][rr * 2], acc[mi][nj][rr * 2 + 1]);
                    *(float2*)&C[(size_t)m * DD + n] = v;
                }
            }
    }
}

// ---------------------------------------------------------------------------
// TF32 flash attention — byte-identical to the R9 passing version (636us).
// Block = (b, h, 128-row Q tile), 256 threads (8 warps).
// ---------------------------------------------------------------------------
#define FSTR 68
#define FA_SMEM_BYTES ((128 + 64 + 64 + 128) * FSTR * 4)   // 104448 B

__global__ __launch_bounds__(256) void flash_tf32(const float* __restrict__ Q,
                                                  const float* __restrict__ K,
                                                  const float* __restrict__ V,
                                                  const int* __restrict__ vlens,
                                                  float* __restrict__ O)
{
    extern __shared__ unsigned sm[];
    unsigned (*Qs)[FSTR] = (unsigned (*)[FSTR])(sm);
    unsigned (*Ks)[FSTR] = (unsigned (*)[FSTR])(sm + 128 * FSTR);
    unsigned (*Vs)[FSTR] = (unsigned (*)[FSTR])(sm + 192 * FSTR);
    unsigned (*Ps)[FSTR] = (unsigned (*)[FSTR])(sm + 256 * FSTR);

    const int tid  = threadIdx.x;
    const int lane = tid & 31, warp = tid >> 5;
    const int qt = blockIdx.x, h = blockIdx.y, b = blockIdx.z;
    const int head = b * HH + h;

    const float* Qb = Q + ((size_t)head * SS + qt * 128) * DHH;
    const float* Kb = K + (size_t)head * SS * DHH;
    const float* Vb = V + (size_t)head * SS * DHH;
    const int   vlen = vlens[b];
    const int   g = lane >> 2, t = lane & 3;
    const int   wrow = warp * 16;
    const float scale = 0.125f;

#pragma unroll
    for (int it = 0; it < 8; it++) {
        int idx = tid + it * 256;
        int row = idx >> 4;
        int c   = (idx & 15) << 2;
        float4 v = *(const float4*)(Qb + (size_t)row * DHH + c);
        Qs[row][c + 0] = f2tf(v.x); Qs[row][c + 1] = f2tf(v.y);
        Qs[row][c + 2] = f2tf(v.z); Qs[row][c + 3] = f2tf(v.w);
    }

    float o[8][4];
#pragma unroll
    for (int nj = 0; nj < 8; nj++)
#pragma unroll
        for (int r = 0; r < 4; r++) o[nj][r] = 0.0f;
    float m0 = -1e30f, m1 = -1e30f, l0 = 0.0f, l1 = 0.0f;

    for (int kb = 0; kb < SS; kb += 64) {
        __syncthreads();
#pragma unroll
        for (int it = 0; it < 4; it++) {
            int idx = tid + it * 256;
            int row = idx >> 4;
            int c   = (idx & 15) << 2;
            float4 vk = *(const float4*)(Kb + (size_t)(kb + row) * DHH + c);
            Ks[row][c + 0] = f2tf(vk.x); Ks[row][c + 1] = f2tf(vk.y);
            Ks[row][c + 2] = f2tf(vk.z); Ks[row][c + 3] = f2tf(vk.w);
            float4 vv = *(const float4*)(Vb + (size_t)(kb + row) * DHH + c);
            Vs[row][c + 0] = f2tf(vv.x); Vs[row][c + 1] = f2tf(vv.y);
            Vs[row][c + 2] = f2tf(vv.z); Vs[row][c + 3] = f2tf(vv.w);
        }
        __syncthreads();

        float s[8][4];
#pragma unroll
        for (int nj = 0; nj < 8; nj++)
#pragma unroll
            for (int r = 0; r < 4; r++) s[nj][r] = 0.0f;

#pragma unroll
        for (int ks = 0; ks < DHH; ks += 8) {
            unsigned a[4];
            a[0] = Qs[wrow + g][ks + t];
            a[1] = Qs[wrow + g + 8][ks + t];
            a[2] = Qs[wrow + g][ks + t + 4];
            a[3] = Qs[wrow + g + 8][ks + t + 4];
#pragma unroll
            for (int nj = 0; nj < 8; nj++) {
                unsigned bf[2];
                bf[0] = Ks[nj * 8 + g][ks + t];
                bf[1] = Ks[nj * 8 + g][ks + t + 4];
                mma8(s[nj], a, bf);
            }
        }

        float rmax0 = -1e30f, rmax1 = -1e30f;
#pragma unroll
        for (int nj = 0; nj < 8; nj++) {
            int c0 = kb + nj * 8 + 2 * t;
            bool v0 = c0 < vlen, v1 = (c0 + 1) < vlen;
            s[nj][0] = v0 ? s[nj][0] * scale : MASKV;
            s[nj][1] = v1 ? s[nj][1] * scale : MASKV;
            s[nj][2] = v0 ? s[nj][2] * scale : MASKV;
            s[nj][3] = v1 ? s[nj][3] * scale : MASKV;
            rmax0 = fmaxf(rmax0, fmaxf(s[nj][0], s[nj][1]));
            rmax1 = fmaxf(rmax1, fmaxf(s[nj][2], s[nj][3]));
        }
        rmax0 = fmaxf(rmax0, __shfl_xor_sync(0xffffffffu, rmax0, 1));
        rmax0 = fmaxf(rmax0, __shfl_xor_sync(0xffffffffu, rmax0, 2));
        rmax1 = fmaxf(rmax1, __shfl_xor_sync(0xffffffffu, rmax1, 1));
        rmax1 = fmaxf(rmax1, __shfl_xor_sync(0xffffffffu, rmax1, 2));

        float mn0 = fmaxf(m0, rmax0), mn1 = fmaxf(m1, rmax1);
        float corr0 = __expf(m0 - mn0), corr1 = __expf(m1 - mn1);
        float rs0 = 0.0f, rs1 = 0.0f;

#pragma unroll
        for (int nj = 0; nj < 8; nj++) {
            float p0 = __expf(s[nj][0] - mn0);
            float p1 = __expf(s[nj][1] - mn0);
            float p2 = __expf(s[nj][2] - mn1);
            float p3 = __expf(s[nj][3] - mn1);
            rs0 += p0 + p1;
            rs1 += p2 + p3;
            *(uint2*)&Ps[wrow + g][nj * 8 + 2 * t]     = make_uint2(f2tf(p0), f2tf(p1));
            *(uint2*)&Ps[wrow + g + 8][nj * 8 + 2 * t] = make_uint2(f2tf(p2), f2tf(p3));
        }
        rs0 += __shfl_xor_sync(0xffffffffu, rs0, 1);
        rs0 += __shfl_xor_sync(0xffffffffu, rs0, 2);
        rs1 += __shfl_xor_sync(0xffffffffu, rs1, 1);
        rs1 += __shfl_xor_sync(0xffffffffu, rs1, 2);

        l0 = l0 * corr0 + rs0;
        l1 = l1 * corr1 + rs1;
        m0 = mn0; m1 = mn1;
#pragma unroll
        for (int nj = 0; nj < 8; nj++) {
            o[nj][0] *= corr0; o[nj][1] *= corr0;
            o[nj][2] *= corr1; o[nj][3] *= corr1;
        }

        __syncwarp();

#pragma unroll
        for (int ks = 0; ks < 64; ks += 8) {
            unsigned a[4];
            a[0] = Ps[wrow + g][ks + t];
            a[1] = Ps[wrow + g + 8][ks + t];
            a[2] = Ps[wrow + g][ks + t + 4];
            a[3] = Ps[wrow + g + 8][ks + t + 4];
#pragma unroll
            for (int nj = 0; nj < 8; nj++) {
                unsigned bf[2];
                bf[0] = Vs[ks + t][nj * 8 + g];
                bf[1] = Vs[ks + t + 4][nj * 8 + g];
                mma8(o[nj], a, bf);
            }
        }
    }

    float inv0 = 1.0f / l0, inv1 = 1.0f / l1;
    int row0 = qt * 128 + wrow + g;
    size_t base0 = ((size_t)b * SS + row0) * DD + h * DHH;
    size_t base1 = base0 + (size_t)8 * DD;
#pragma unroll
    for (int nj = 0; nj < 8; nj++) {
        *(float2*)&O[base0 + nj * 8 + 2 * t] = make_float2(o[nj][0] * inv0, o[nj][1] * inv0);
        *(float2*)&O[base1 + nj * 8 + 2 * t] = make_float2(o[nj][2] * inv1, o[nj][3] * inv1);
    }
}

// ---------------------------------------------------------------------------
// Launch. Inputs (metadata order): key, query, value, valid_lens, Wk, Wq, Wv, Wo
// ---------------------------------------------------------------------------
extern "C" void kernel_launch(void* const* d_in, const int* in_sizes, int n_in,
                              void* d_out, int out_size)
{
    const float* key_   = (const float*)d_in[0];
    const float* query_ = (const float*)d_in[1];
    const float* value_ = (const float*)d_in[2];
    const int*   vlens  = (const int*)  d_in[3];
    const float* Wk     = (const float*)d_in[4];
    const float* Wq     = (const float*)d_in[5];
    const float* Wv     = (const float*)d_in[6];
    const float* Wo     = (const float*)d_in[7];
    float* out = (float*)d_out;

    float *qh, *kh, *vh, *oc;
    cudaGetSymbolAddress((void**)&qh, g_Qh);
    cudaGetSymbolAddress((void**)&kh, g_Kh);
    cudaGetSymbolAddress((void**)&vh, g_Vh);
    cudaGetSymbolAddress((void**)&oc, g_Oc);

    cudaFuncSetAttribute(gemm_cp, cudaFuncAttributeMaxDynamicSharedMemorySize,
                         G_SMEM_BYTES);
    cudaFuncSetAttribute(flash_tf32, cudaFuncAttributeMaxDynamicSharedMemorySize,
                         FA_SMEM_BYTES);

    // Fused Q/K/V projections (grid z selects operand set)
    GArgs pa;
    pa.A[0] = query_; pa.A[1] = key_; pa.A[2] = value_;
    pa.W[0] = Wq;     pa.W[1] = Wk;   pa.W[2] = Wv;
    pa.C[0] = qh;     pa.C[1] = kh;   pa.C[2] = vh;
    pa.mode = 0;
    gemm_cp<<<dim3(DD / 128, MM / 128, 3), 256, G_SMEM_BYTES>>>(pa);

    dim3 ga(SS / 128, HH, BB);    // (16, 16, 4)
    flash_tf32<<<ga, 256, FA_SMEM_BYTES>>>(qh, kh, vh, vlens, oc);

    // Output projection
    GArgs po;
    po.A[0] = po.A[1] = po.A[2] = oc;
    po.W[0] = po.W[1] = po.W[2] = Wo;
    po.C[0] = po.C[1] = po.C[2] = out;
    po.mode = 1;
    gemm_cp<<<dim3(DD / 128, MM / 128, 1), 256, G_SMEM_BYTES>>>(po);
}

// round 12
// speedup vs baseline: 4.4025x; 1.3434x over previous
#include <cuda_runtime.h>
#include <math.h>
#include <stdint.h>

// Problem constants
#define BB   4
#define SS   2048
#define DD   1024
#define HH   16
#define DHH  64
#define MM   (BB * SS)          // 8192 rows
#define MASKV (-1000000.0f)

// Scratch (device globals: allocation-free rule)
__device__ float g_Qh[(size_t)MM * DD];  // [B,H,S,DH] head-split
__device__ float g_Kh[(size_t)MM * DD];
__device__ float g_Vh[(size_t)MM * DD];
__device__ float g_Oc[(size_t)MM * DD];  // [B,S,D] concat-head attention output

// ---------------------------------------------------------------------------
// Helpers
// ---------------------------------------------------------------------------
__device__ __forceinline__ uint32_t smem_u32(const void* p) {
    uint32_t a;
    asm("{ .reg .u64 t; cvta.to.shared.u64 t, %1; cvt.u32.u64 %0, t; }" : "=r"(a) : "l"(p));
    return a;
}
__device__ __forceinline__ unsigned f2tf(float x) {
    unsigned u;
    asm("cvt.rna.tf32.f32 %0, %1;" : "=r"(u) : "f"(x));
    return u;
}
__device__ __forceinline__ void mma8(float* d, const unsigned* a, const unsigned* b) {
    asm volatile(
        "mma.sync.aligned.m16n8k8.row.col.f32.tf32.tf32.f32 "
        "{%0,%1,%2,%3}, {%4,%5,%6,%7}, {%8,%9}, {%0,%1,%2,%3};"
        : "+f"(d[0]), "+f"(d[1]), "+f"(d[2]), "+f"(d[3])
        : "r"(a[0]), "r"(a[1]), "r"(a[2]), "r"(a[3]), "r"(b[0]), "r"(b[1]));
}
__device__ __forceinline__ void cpa16(uint32_t dst, const float* src) {
    asm volatile("cp.async.cg.shared.global [%0], [%1], 16;" :: "r"(dst), "l"(src));
}
#define CPA_COMMIT() asm volatile("cp.async.commit_group;" ::: "memory")
#define CPA_WAIT1()  asm volatile("cp.async.wait_group 1;" ::: "memory")
#define CPA_WAIT0()  asm volatile("cp.async.wait_group 0;" ::: "memory")

// ---------------------------------------------------------------------------
// TF32 NT GEMM, 3-stage cp.async pipeline — byte-identical to R11 (passed).
// ---------------------------------------------------------------------------
struct GArgs { const float* A[3]; const float* W[3]; float* C[3]; int mode; };

#define GBK  32
#define GSTR 36
#define G_STAGE_W (2 * 128 * GSTR)                  // 9216 words per stage
#define G_SMEM_BYTES (3 * G_STAGE_W * 4)            // 110592 B

__global__ __launch_bounds__(256, 2) void gemm_cp(GArgs args)
{
    extern __shared__ float gsm[];
    const uint32_t sb = smem_u32(gsm);
    const int tid  = threadIdx.x;
    const int lane = tid & 31, warp = tid >> 5;
    const int z  = blockIdx.z;
    const float* __restrict__ A = args.A[z];
    const float* __restrict__ W = args.W[z];
    float* __restrict__ C = args.C[z];
    const int mode = args.mode;
    const int bm = blockIdx.y * 128, bn = blockIdx.x * 128;
    const int wm = (warp >> 1) * 32, wn = (warp & 1) * 64;
    const int g = lane >> 2, t = lane & 3;

    int ar[4], ac[4];
#pragma unroll
    for (int i = 0; i < 4; i++) {
        int idx = tid + i * 256;
        ar[i] = idx >> 3;
        ac[i] = (idx & 7) << 2;
    }

#define G_ISSUE(ktile, stg) do {                                               \
    uint32_t base_ = sb + (uint32_t)(stg) * (G_STAGE_W * 4);                   \
    const float* As_ = A + (size_t)bm * DD + (ktile) * GBK;                    \
    const float* Ws_ = W + (size_t)bn * DD + (ktile) * GBK;                    \
    _Pragma("unroll")                                                          \
    for (int i_ = 0; i_ < 4; i_++) {                                           \
        cpa16(base_ + (uint32_t)((ar[i_] * GSTR + ac[i_]) * 4),                \
              As_ + (size_t)ar[i_] * DD + ac[i_]);                             \
        cpa16(base_ + (uint32_t)((128 * GSTR + ar[i_] * GSTR + ac[i_]) * 4),   \
              Ws_ + (size_t)ar[i_] * DD + ac[i_]);                             \
    }                                                                          \
    CPA_COMMIT();                                                              \
} while (0)

    float acc[2][8][4];
#pragma unroll
    for (int mi = 0; mi < 2; mi++)
#pragma unroll
        for (int nj = 0; nj < 8; nj++)
#pragma unroll
            for (int r = 0; r < 4; r++) acc[mi][nj][r] = 0.0f;

    G_ISSUE(0, 0);
    G_ISSUE(1, 1);

    const int NT = DD / GBK;   // 32
    for (int kt = 0; kt < NT; kt++) {
        if (kt < NT - 1) { CPA_WAIT1(); } else { CPA_WAIT0(); }
        __syncthreads();
        if (kt + 2 < NT) G_ISSUE(kt + 2, (kt + 2) % 3);

        const float* Ast = gsm + (kt % 3) * G_STAGE_W;
        const float* Bst = Ast + 128 * GSTR;
#pragma unroll
        for (int ks = 0; ks < GBK; ks += 8) {
            unsigned a[2][4], b[8][2];
#pragma unroll
            for (int mi = 0; mi < 2; mi++) {
                int r0 = (wm + mi * 16 + g) * GSTR;
                int r8 = (wm + mi * 16 + g + 8) * GSTR;
                a[mi][0] = f2tf(Ast[r0 + ks + t]);
                a[mi][1] = f2tf(Ast[r8 + ks + t]);
                a[mi][2] = f2tf(Ast[r0 + ks + t + 4]);
                a[mi][3] = f2tf(Ast[r8 + ks + t + 4]);
            }
#pragma unroll
            for (int nj = 0; nj < 8; nj++) {
                int c0 = (wn + nj * 8 + g) * GSTR;
                b[nj][0] = f2tf(Bst[c0 + ks + t]);
                b[nj][1] = f2tf(Bst[c0 + ks + t + 4]);
            }
#pragma unroll
            for (int mi = 0; mi < 2; mi++)
#pragma unroll
                for (int nj = 0; nj < 8; nj++)
                    mma8(acc[mi][nj], a[mi], b[nj]);
        }
    }
#undef G_ISSUE

    if (mode == 0) {
#pragma unroll
        for (int mi = 0; mi < 2; mi++)
#pragma unroll
            for (int rr = 0; rr < 2; rr++) {
                int m  = bm + wm + mi * 16 + g + rr * 8;
                int b_ = m >> 11;
                int s_ = m & (SS - 1);
#pragma unroll
                for (int nj = 0; nj < 8; nj++) {
                    int n  = bn + wn + nj * 8 + 2 * t;
                    int h_ = n >> 6;
                    int dh = n & 63;
                    float2 v = make_float2(acc[mi][nj][rr * 2], acc[mi][nj][rr * 2 + 1]);
                    *(float2*)&C[(((size_t)b_ * HH + h_) * SS + s_) * DHH + dh] = v;
                }
            }
    } else {
#pragma unroll
        for (int mi = 0; mi < 2; mi++)
#pragma unroll
            for (int rr = 0; rr < 2; rr++) {
                int m = bm + wm + mi * 16 + g + rr * 8;
#pragma unroll
                for (int nj = 0; nj < 8; nj++) {
                    int n = bn + wn + nj * 8 + 2 * t;
                    float2 v = make_float2(acc[mi][nj][rr * 2], acc[mi][nj][rr * 2 + 1]);
                    *(float2*)&C[(size_t)m * DD + n] = v;
                }
            }
    }
}

// ---------------------------------------------------------------------------
// TF32 flash attention v3 (based on R9-proven structure):
//  * masked K-block skipping: blocks with kb >= vlen contribute exact 0
//    (expf underflow) -> loop runs nb = ceil(vlen/64) blocks (all 32 if
//    vlen==0 to reproduce the uniform-softmax case). Bit-identical output.
//  * vectorized staging: K/Q STS.128 (conflict-free), V packed uint2 pairs.
//  * V pair-row layout VP[q][c] = (V[r][c], V[r+4][c]) -> PV B-frags are
//    single conflict-free LDS.64 (was 2x 2-way LDS.32).
//  * b mapped to blockIdx.x so unequal-vlen CTAs interleave across waves.
// smem words: Qs [128][68] | Ks [64][68] | VP 32*68*2 | Ps [128][68]
// ---------------------------------------------------------------------------
#define FSTR 68
#define FQ_W 0
#define FK_W 8704
#define FV_W (8704 + 4352)
#define FP_W (8704 + 4352 + 4352)
#define FA_SMEM_BYTES ((8704 + 4352 + 4352 + 8704) * 4)   // 104448 B

__global__ __launch_bounds__(256) void flash_tf32(const float* __restrict__ Q,
                                                  const float* __restrict__ K,
                                                  const float* __restrict__ V,
                                                  const int* __restrict__ vlens,
                                                  float* __restrict__ O)
{
    extern __shared__ unsigned sm[];
    unsigned (*Qs)[FSTR] = (unsigned (*)[FSTR])(sm + FQ_W);
    unsigned (*Ks)[FSTR] = (unsigned (*)[FSTR])(sm + FK_W);
    unsigned* Vsp        = sm + FV_W;   // VP[q][c] uint2 pairs, q-stride 68
    unsigned (*Ps)[FSTR] = (unsigned (*)[FSTR])(sm + FP_W);

    const int tid  = threadIdx.x;
    const int lane = tid & 31, warp = tid >> 5;
    const int b = blockIdx.x, h = blockIdx.y, qt = blockIdx.z;
    const int head = b * HH + h;

    const float* Qb = Q + ((size_t)head * SS + qt * 128) * DHH;
    const float* Kb = K + (size_t)head * SS * DHH;
    const float* Vb = V + (size_t)head * SS * DHH;
    const int   vlen = vlens[b];
    const int   g = lane >> 2, t = lane & 3;
    const int   wrow = warp * 16;
    const float scale = 0.125f;

    // Q tile -> tf32 smem, vectorized STS.128
#pragma unroll
    for (int it = 0; it < 8; it++) {
        int idx = tid + it * 256;
        int row = idx >> 4;
        int c   = (idx & 15) << 2;
        float4 v = *(const float4*)(Qb + (size_t)row * DHH + c);
        *(uint4*)&Qs[row][c] = make_uint4(f2tf(v.x), f2tf(v.y), f2tf(v.z), f2tf(v.w));
    }

    float o[8][4];
#pragma unroll
    for (int nj = 0; nj < 8; nj++)
#pragma unroll
        for (int r = 0; r < 4; r++) o[nj][r] = 0.0f;
    float m0 = -1e30f, m1 = -1e30f, l0 = 0.0f, l1 = 0.0f;

    // Masked-block skip: blocks past vlen contribute exactly 0 (expf
    // underflow). vlen==0 -> all scores masked -> uniform softmax needs
    // every block processed.
    const int nb = (vlen == 0) ? (SS / 64) : ((vlen + 63) >> 6);

    for (int kbi = 0; kbi < nb; kbi++) {
        const int kb = kbi * 64;
        __syncthreads();
        // K staging: plain layout, STS.128 (conflict-free)
#pragma unroll
        for (int it = 0; it < 4; it++) {
            int idx = tid + it * 256;
            int row = idx >> 4;
            int c   = (idx & 15) << 2;
            float4 vk = *(const float4*)(Kb + (size_t)(kb + row) * DHH + c);
            *(uint4*)&Ks[row][c] = make_uint4(f2tf(vk.x), f2tf(vk.y), f2tf(vk.z), f2tf(vk.w));
        }
        // V staging: pair-row layout. unit -> (q, 4-col quad); rows r0=q-decoded, r1=r0+4.
#pragma unroll
        for (int it = 0; it < 2; it++) {
            int u  = tid + it * 256;            // 0..511
            int q  = u >> 4;                    // 0..31
            int c  = (u & 15) << 2;             // 0..60
            int r0 = ((q >> 2) << 3) + (q & 3); // pair base row
            const float* Vr = Vb + (size_t)(kb + r0) * DHH + c;
            float4 v0 = *(const float4*)(Vr);
            float4 v1 = *(const float4*)(Vr + 4 * DHH);
            unsigned* base = Vsp + (q * FSTR + c) * 2;
            *(uint2*)(base + 0) = make_uint2(f2tf(v0.x), f2tf(v1.x));
            *(uint2*)(base + 2) = make_uint2(f2tf(v0.y), f2tf(v1.y));
            *(uint2*)(base + 4) = make_uint2(f2tf(v0.z), f2tf(v1.z));
            *(uint2*)(base + 6) = make_uint2(f2tf(v0.w), f2tf(v1.w));
        }
        __syncthreads();

        // S = Q @ K^T
        float s[8][4];
#pragma unroll
        for (int nj = 0; nj < 8; nj++)
#pragma unroll
            for (int r = 0; r < 4; r++) s[nj][r] = 0.0f;

#pragma unroll
        for (int ks = 0; ks < DHH; ks += 8) {
            unsigned a[4];
            a[0] = Qs[wrow + g][ks + t];
            a[1] = Qs[wrow + g + 8][ks + t];
            a[2] = Qs[wrow + g][ks + t + 4];
            a[3] = Qs[wrow + g + 8][ks + t + 4];
#pragma unroll
            for (int nj = 0; nj < 8; nj++) {
                unsigned bf[2];
                bf[0] = Ks[nj * 8 + g][ks + t];
                bf[1] = Ks[nj * 8 + g][ks + t + 4];
                mma8(s[nj], a, bf);
            }
        }

        // scale + mask (reference semantics: masked -> -1e6, unscaled)
        float rmax0 = -1e30f, rmax1 = -1e30f;
#pragma unroll
        for (int nj = 0; nj < 8; nj++) {
            int c0 = kb + nj * 8 + 2 * t;
            bool v0 = c0 < vlen, v1 = (c0 + 1) < vlen;
            s[nj][0] = v0 ? s[nj][0] * scale : MASKV;
            s[nj][1] = v1 ? s[nj][1] * scale : MASKV;
            s[nj][2] = v0 ? s[nj][2] * scale : MASKV;
            s[nj][3] = v1 ? s[nj][3] * scale : MASKV;
            rmax0 = fmaxf(rmax0, fmaxf(s[nj][0], s[nj][1]));
            rmax1 = fmaxf(rmax1, fmaxf(s[nj][2], s[nj][3]));
        }
        rmax0 = fmaxf(rmax0, __shfl_xor_sync(0xffffffffu, rmax0, 1));
        rmax0 = fmaxf(rmax0, __shfl_xor_sync(0xffffffffu, rmax0, 2));
        rmax1 = fmaxf(rmax1, __shfl_xor_sync(0xffffffffu, rmax1, 1));
        rmax1 = fmaxf(rmax1, __shfl_xor_sync(0xffffffffu, rmax1, 2));

        float mn0 = fmaxf(m0, rmax0), mn1 = fmaxf(m1, rmax1);
        float corr0 = __expf(m0 - mn0), corr1 = __expf(m1 - mn1);
        float rs0 = 0.0f, rs1 = 0.0f;

#pragma unroll
        for (int nj = 0; nj < 8; nj++) {
            float p0 = __expf(s[nj][0] - mn0);
            float p1 = __expf(s[nj][1] - mn0);
            float p2 = __expf(s[nj][2] - mn1);
            float p3 = __expf(s[nj][3] - mn1);
            rs0 += p0 + p1;
            rs1 += p2 + p3;
            *(uint2*)&Ps[wrow + g][nj * 8 + 2 * t]     = make_uint2(f2tf(p0), f2tf(p1));
            *(uint2*)&Ps[wrow + g + 8][nj * 8 + 2 * t] = make_uint2(f2tf(p2), f2tf(p3));
        }
        rs0 += __shfl_xor_sync(0xffffffffu, rs0, 1);
        rs0 += __shfl_xor_sync(0xffffffffu, rs0, 2);
        rs1 += __shfl_xor_sync(0xffffffffu, rs1, 1);
        rs1 += __shfl_xor_sync(0xffffffffu, rs1, 2);

        l0 = l0 * corr0 + rs0;
        l1 = l1 * corr1 + rs1;
        m0 = mn0; m1 = mn1;
#pragma unroll
        for (int nj = 0; nj < 8; nj++) {
            o[nj][0] *= corr0; o[nj][1] *= corr0;
            o[nj][2] *= corr1; o[nj][3] *= corr1;
        }

        __syncwarp();

        // O += P @ V  (V B-frags: single LDS.64 from pair layout)
#pragma unroll
        for (int ks = 0; ks < 64; ks += 8) {
            unsigned a[4];
            a[0] = Ps[wrow + g][ks + t];
            a[1] = Ps[wrow + g + 8][ks + t];
            a[2] = Ps[wrow + g][ks + t + 4];
            a[3] = Ps[wrow + g + 8][ks + t + 4];
            const int q = (ks >> 1) + t;     // = 4*(ks/8) + t
#pragma unroll
            for (int nj = 0; nj < 8; nj++) {
                uint2 bv = *(uint2*)(Vsp + (q * FSTR + nj * 8 + g) * 2);
                unsigned bf[2] = { bv.x, bv.y };
                mma8(o[nj], a, bf);
            }
        }
    }

    // Normalize, write concat-head [B,S,D]
    float inv0 = 1.0f / l0, inv1 = 1.0f / l1;
    int row0 = qt * 128 + wrow + g;
    size_t base0 = ((size_t)b * SS + row0) * DD + h * DHH;
    size_t base1 = base0 + (size_t)8 * DD;
#pragma unroll
    for (int nj = 0; nj < 8; nj++) {
        *(float2*)&O[base0 + nj * 8 + 2 * t] = make_float2(o[nj][0] * inv0, o[nj][1] * inv0);
        *(float2*)&O[base1 + nj * 8 + 2 * t] = make_float2(o[nj][2] * inv1, o[nj][3] * inv1);
    }
}

// ---------------------------------------------------------------------------
// Launch. Inputs (metadata order): key, query, value, valid_lens, Wk, Wq, Wv, Wo
// ---------------------------------------------------------------------------
extern "C" void kernel_launch(void* const* d_in, const int* in_sizes, int n_in,
                              void* d_out, int out_size)
{
    const float* key_   = (const float*)d_in[0];
    const float* query_ = (const float*)d_in[1];
    const float* value_ = (const float*)d_in[2];
    const int*   vlens  = (const int*)  d_in[3];
    const float* Wk     = (const float*)d_in[4];
    const float* Wq     = (const float*)d_in[5];
    const float* Wv     = (const float*)d_in[6];
    const float* Wo     = (const float*)d_in[7];
    float* out = (float*)d_out;

    float *qh, *kh, *vh, *oc;
    cudaGetSymbolAddress((void**)&qh, g_Qh);
    cudaGetSymbolAddress((void**)&kh, g_Kh);
    cudaGetSymbolAddress((void**)&vh, g_Vh);
    cudaGetSymbolAddress((void**)&oc, g_Oc);

    cudaFuncSetAttribute(gemm_cp, cudaFuncAttributeMaxDynamicSharedMemorySize,
                         G_SMEM_BYTES);
    cudaFuncSetAttribute(flash_tf32, cudaFuncAttributeMaxDynamicSharedMemorySize,
                         FA_SMEM_BYTES);

    // Fused Q/K/V projections (grid z selects operand set)
    GArgs pa;
    pa.A[0] = query_; pa.A[1] = key_; pa.A[2] = value_;
    pa.W[0] = Wq;     pa.W[1] = Wk;   pa.W[2] = Wv;
    pa.C[0] = qh;     pa.C[1] = kh;   pa.C[2] = vh;
    pa.mode = 0;
    gemm_cp<<<dim3(DD / 128, MM / 128, 3), 256, G_SMEM_BYTES>>>(pa);

    // b on blockIdx.x so different-vlen CTAs interleave within each wave
    dim3 ga(BB, HH, SS / 128);    // (4, 16, 16)
    flash_tf32<<<ga, 256, FA_SMEM_BYTES>>>(qh, kh, vh, vlens, oc);

    // Output projection
    GArgs po;
    po.A[0] = po.A[1] = po.A[2] = oc;
    po.W[0] = po.W[1] = po.W[2] = Wo;
    po.C[0] = po.C[1] = po.C[2] = out;
    po.mode = 1;
    gemm_cp<<<dim3(DD / 128, MM / 128, 1), 256, G_SMEM_BYTES>>>(po);
}

// round 13
// speedup vs baseline: 4.6768x; 1.0623x over previous
#include <cuda_runtime.h>
#include <math.h>
#include <stdint.h>

// Problem constants
#define BB   4
#define SS   2048
#define DD   1024
#define HH   16
#define DHH  64
#define MM   (BB * SS)          // 8192 rows
#define MASKV (-1000000.0f)

// Scratch (device globals: allocation-free rule)
__device__ float    g_Qh[(size_t)MM * DD];  // [B,H,S,DH] head-split
__device__ float    g_Kh[(size_t)MM * DD];
__device__ float    g_Vh[(size_t)MM * DD];
__device__ float    g_Oc[(size_t)MM * DD];  // [B,S,D] concat-head attention output
__device__ unsigned g_Wt[(size_t)4 * DD * DD];  // tf32 pre-converted Wq,Wk,Wv,Wo

// ---------------------------------------------------------------------------
// Helpers
// ---------------------------------------------------------------------------
__device__ __forceinline__ uint32_t smem_u32(const void* p) {
    uint32_t a;
    asm("{ .reg .u64 t; cvta.to.shared.u64 t, %1; cvt.u32.u64 %0, t; }" : "=r"(a) : "l"(p));
    return a;
}
__device__ __forceinline__ unsigned f2tf(float x) {
    unsigned u;
    asm("cvt.rna.tf32.f32 %0, %1;" : "=r"(u) : "f"(x));
    return u;
}
__device__ __forceinline__ void mma8(float* d, const unsigned* a, const unsigned* b) {
    asm volatile(
        "mma.sync.aligned.m16n8k8.row.col.f32.tf32.tf32.f32 "
        "{%0,%1,%2,%3}, {%4,%5,%6,%7}, {%8,%9}, {%0,%1,%2,%3};"
        : "+f"(d[0]), "+f"(d[1]), "+f"(d[2]), "+f"(d[3])
        : "r"(a[0]), "r"(a[1]), "r"(a[2]), "r"(a[3]), "r"(b[0]), "r"(b[1]));
}
__device__ __forceinline__ void cpa16(uint32_t dst, const void* src) {
    asm volatile("cp.async.cg.shared.global [%0], [%1], 16;" :: "r"(dst), "l"(src));
}
#define CPA_COMMIT() asm volatile("cp.async.commit_group;" ::: "memory")
#define CPA_WAIT1()  asm volatile("cp.async.wait_group 1;" ::: "memory")
#define CPA_WAIT0()  asm volatile("cp.async.wait_group 0;" ::: "memory")

// ---------------------------------------------------------------------------
// Weight pre-convert: fp32 -> tf32 bits, once per run (~16MB traffic).
// grid (1024, 4) x 256: y selects which W; x*256+tid indexes float4s.
// ---------------------------------------------------------------------------
struct CArgs { const float* W[4]; };

__global__ __launch_bounds__(256) void cvt_w(CArgs a, unsigned* __restrict__ out)
{
    const int w = blockIdx.y;
    const int i = blockIdx.x * 256 + threadIdx.x;       // 0..262143
    float4 v = ((const float4*)a.W[w])[i];
    uint4 u = make_uint4(f2tf(v.x), f2tf(v.y), f2tf(v.z), f2tf(v.w));
    ((uint4*)(out + (size_t)w * DD * DD))[i] = u;
}

// ---------------------------------------------------------------------------
// TF32 NT GEMM, 3-stage cp.async pipeline: C[m,n] = sum_k A[m,k] * W[n,k]
// A: fp32 (cvt at consume). W: PRE-CONVERTED tf32 bits (no cvt in loop).
// 128x128 tile, BK=32, 256 threads (8 warps, warp tile 32x64), 2 CTAs/SM.
// mode 0: head-split [B,H,S,DH]; mode 1: row-major [M,1024]
// ---------------------------------------------------------------------------
struct GArgs { const float* A[3]; const unsigned* W[3]; float* C[3]; int mode; };

#define GBK  32
#define GSTR 36
#define G_STAGE_W (2 * 128 * GSTR)                  // 9216 words per stage
#define G_SMEM_BYTES (3 * G_STAGE_W * 4)            // 110592 B

__global__ __launch_bounds__(256, 2) void gemm_cp(GArgs args)
{
    extern __shared__ float gsm[];
    const uint32_t sb = smem_u32(gsm);
    const int tid  = threadIdx.x;
    const int lane = tid & 31, warp = tid >> 5;
    const int z  = blockIdx.z;
    const float*    __restrict__ A = args.A[z];
    const unsigned* __restrict__ W = args.W[z];
    float* __restrict__ C = args.C[z];
    const int mode = args.mode;
    const int bm = blockIdx.y * 128, bn = blockIdx.x * 128;
    const int wm = (warp >> 1) * 32, wn = (warp & 1) * 64;
    const int g = lane >> 2, t = lane & 3;

    int ar[4], ac[4];
#pragma unroll
    for (int i = 0; i < 4; i++) {
        int idx = tid + i * 256;
        ar[i] = idx >> 3;
        ac[i] = (idx & 7) << 2;
    }

#define G_ISSUE(ktile, stg) do {                                               \
    uint32_t base_ = sb + (uint32_t)(stg) * (G_STAGE_W * 4);                   \
    const float*    As_ = A + (size_t)bm * DD + (ktile) * GBK;                 \
    const unsigned* Ws_ = W + (size_t)bn * DD + (ktile) * GBK;                 \
    _Pragma("unroll")                                                          \
    for (int i_ = 0; i_ < 4; i_++) {                                           \
        cpa16(base_ + (uint32_t)((ar[i_] * GSTR + ac[i_]) * 4),                \
              As_ + (size_t)ar[i_] * DD + ac[i_]);                             \
        cpa16(base_ + (uint32_t)((128 * GSTR + ar[i_] * GSTR + ac[i_]) * 4),   \
              Ws_ + (size_t)ar[i_] * DD + ac[i_]);                             \
    }                                                                          \
    CPA_COMMIT();                                                              \
} while (0)

    float acc[2][8][4];
#pragma unroll
    for (int mi = 0; mi < 2; mi++)
#pragma unroll
        for (int nj = 0; nj < 8; nj++)
#pragma unroll
            for (int r = 0; r < 4; r++) acc[mi][nj][r] = 0.0f;

    G_ISSUE(0, 0);
    G_ISSUE(1, 1);

    const int NT = DD / GBK;   // 32
    for (int kt = 0; kt < NT; kt++) {
        if (kt < NT - 1) { CPA_WAIT1(); } else { CPA_WAIT0(); }
        __syncthreads();
        if (kt + 2 < NT) G_ISSUE(kt + 2, (kt + 2) % 3);

        const float*    Ast = gsm + (kt % 3) * G_STAGE_W;
        const unsigned* Bst = (const unsigned*)(Ast + 128 * GSTR);
#pragma unroll
        for (int ks = 0; ks < GBK; ks += 8) {
            unsigned a[2][4], b[8][2];
#pragma unroll
            for (int mi = 0; mi < 2; mi++) {
                int r0 = (wm + mi * 16 + g) * GSTR;
                int r8 = (wm + mi * 16 + g + 8) * GSTR;
                a[mi][0] = f2tf(Ast[r0 + ks + t]);
                a[mi][1] = f2tf(Ast[r8 + ks + t]);
                a[mi][2] = f2tf(Ast[r0 + ks + t + 4]);
                a[mi][3] = f2tf(Ast[r8 + ks + t + 4]);
            }
#pragma unroll
            for (int nj = 0; nj < 8; nj++) {
                int c0 = (wn + nj * 8 + g) * GSTR;
                b[nj][0] = Bst[c0 + ks + t];        // pre-converted tf32 bits
                b[nj][1] = Bst[c0 + ks + t + 4];
            }
#pragma unroll
            for (int mi = 0; mi < 2; mi++)
#pragma unroll
                for (int nj = 0; nj < 8; nj++)
                    mma8(acc[mi][nj], a[mi], b[nj]);
        }
    }
#undef G_ISSUE

    if (mode == 0) {
#pragma unroll
        for (int mi = 0; mi < 2; mi++)
#pragma unroll
            for (int rr = 0; rr < 2; rr++) {
                int m  = bm + wm + mi * 16 + g + rr * 8;
                int b_ = m >> 11;
                int s_ = m & (SS - 1);
#pragma unroll
                for (int nj = 0; nj < 8; nj++) {
                    int n  = bn + wn + nj * 8 + 2 * t;
                    int h_ = n >> 6;
                    int dh = n & 63;
                    float2 v = make_float2(acc[mi][nj][rr * 2], acc[mi][nj][rr * 2 + 1]);
                    *(float2*)&C[(((size_t)b_ * HH + h_) * SS + s_) * DHH + dh] = v;
                }
            }
    } else {
#pragma unroll
        for (int mi = 0; mi < 2; mi++)
#pragma unroll
            for (int rr = 0; rr < 2; rr++) {
                int m = bm + wm + mi * 16 + g + rr * 8;
#pragma unroll
                for (int nj = 0; nj < 8; nj++) {
                    int n = bn + wn + nj * 8 + 2 * t;
                    float2 v = make_float2(acc[mi][nj][rr * 2], acc[mi][nj][rr * 2 + 1]);
                    *(float2*)&C[(size_t)m * DD + n] = v;
                }
            }
    }
}

// ---------------------------------------------------------------------------
// TF32 flash attention v3 — byte-identical to the R12 passing version.
// ---------------------------------------------------------------------------
#define FSTR 68
#define FQ_W 0
#define FK_W 8704
#define FV_W (8704 + 4352)
#define FP_W (8704 + 4352 + 4352)
#define FA_SMEM_BYTES ((8704 + 4352 + 4352 + 8704) * 4)   // 104448 B

__global__ __launch_bounds__(256) void flash_tf32(const float* __restrict__ Q,
                                                  const float* __restrict__ K,
                                                  const float* __restrict__ V,
                                                  const int* __restrict__ vlens,
                                                  float* __restrict__ O)
{
    extern __shared__ unsigned sm[];
    unsigned (*Qs)[FSTR] = (unsigned (*)[FSTR])(sm + FQ_W);
    unsigned (*Ks)[FSTR] = (unsigned (*)[FSTR])(sm + FK_W);
    unsigned* Vsp        = sm + FV_W;   // VP[q][c] uint2 pairs, q-stride 68
    unsigned (*Ps)[FSTR] = (unsigned (*)[FSTR])(sm + FP_W);

    const int tid  = threadIdx.x;
    const int lane = tid & 31, warp = tid >> 5;
    const int b = blockIdx.x, h = blockIdx.y, qt = blockIdx.z;
    const int head = b * HH + h;

    const float* Qb = Q + ((size_t)head * SS + qt * 128) * DHH;
    const float* Kb = K + (size_t)head * SS * DHH;
    const float* Vb = V + (size_t)head * SS * DHH;
    const int   vlen = vlens[b];
    const int   g = lane >> 2, t = lane & 3;
    const int   wrow = warp * 16;
    const float scale = 0.125f;

#pragma unroll
    for (int it = 0; it < 8; it++) {
        int idx = tid + it * 256;
        int row = idx >> 4;
        int c   = (idx & 15) << 2;
        float4 v = *(const float4*)(Qb + (size_t)row * DHH + c);
        *(uint4*)&Qs[row][c] = make_uint4(f2tf(v.x), f2tf(v.y), f2tf(v.z), f2tf(v.w));
    }

    float o[8][4];
#pragma unroll
    for (int nj = 0; nj < 8; nj++)
#pragma unroll
        for (int r = 0; r < 4; r++) o[nj][r] = 0.0f;
    float m0 = -1e30f, m1 = -1e30f, l0 = 0.0f, l1 = 0.0f;

    const int nb = (vlen == 0) ? (SS / 64) : ((vlen + 63) >> 6);

    for (int kbi = 0; kbi < nb; kbi++) {
        const int kb = kbi * 64;
        __syncthreads();
#pragma unroll
        for (int it = 0; it < 4; it++) {
            int idx = tid + it * 256;
            int row = idx >> 4;
            int c   = (idx & 15) << 2;
            float4 vk = *(const float4*)(Kb + (size_t)(kb + row) * DHH + c);
            *(uint4*)&Ks[row][c] = make_uint4(f2tf(vk.x), f2tf(vk.y), f2tf(vk.z), f2tf(vk.w));
        }
#pragma unroll
        for (int it = 0; it < 2; it++) {
            int u  = tid + it * 256;
            int q  = u >> 4;
            int c  = (u & 15) << 2;
            int r0 = ((q >> 2) << 3) + (q & 3);
            const float* Vr = Vb + (size_t)(kb + r0) * DHH + c;
            float4 v0 = *(const float4*)(Vr);
            float4 v1 = *(const float4*)(Vr + 4 * DHH);
            unsigned* base = Vsp + (q * FSTR + c) * 2;
            *(uint2*)(base + 0) = make_uint2(f2tf(v0.x), f2tf(v1.x));
            *(uint2*)(base + 2) = make_uint2(f2tf(v0.y), f2tf(v1.y));
            *(uint2*)(base + 4) = make_uint2(f2tf(v0.z), f2tf(v1.z));
            *(uint2*)(base + 6) = make_uint2(f2tf(v0.w), f2tf(v1.w));
        }
        __syncthreads();

        float s[8][4];
#pragma unroll
        for (int nj = 0; nj < 8; nj++)
#pragma unroll
            for (int r = 0; r < 4; r++) s[nj][r] = 0.0f;

#pragma unroll
        for (int ks = 0; ks < DHH; ks += 8) {
            unsigned a[4];
            a[0] = Qs[wrow + g][ks + t];
            a[1] = Qs[wrow + g + 8][ks + t];
            a[2] = Qs[wrow + g][ks + t + 4];
            a[3] = Qs[wrow + g + 8][ks + t + 4];
#pragma unroll
            for (int nj = 0; nj < 8; nj++) {
                unsigned bf[2];
                bf[0] = Ks[nj * 8 + g][ks + t];
                bf[1] = Ks[nj * 8 + g][ks + t + 4];
                mma8(s[nj], a, bf);
            }
        }

        float rmax0 = -1e30f, rmax1 = -1e30f;
#pragma unroll
        for (int nj = 0; nj < 8; nj++) {
            int c0 = kb + nj * 8 + 2 * t;
            bool v0 = c0 < vlen, v1 = (c0 + 1) < vlen;
            s[nj][0] = v0 ? s[nj][0] * scale : MASKV;
            s[nj][1] = v1 ? s[nj][1] * scale : MASKV;
            s[nj][2] = v0 ? s[nj][2] * scale : MASKV;
            s[nj][3] = v1 ? s[nj][3] * scale : MASKV;
            rmax0 = fmaxf(rmax0, fmaxf(s[nj][0], s[nj][1]));
            rmax1 = fmaxf(rmax1, fmaxf(s[nj][2], s[nj][3]));
        }
        rmax0 = fmaxf(rmax0, __shfl_xor_sync(0xffffffffu, rmax0, 1));
        rmax0 = fmaxf(rmax0, __shfl_xor_sync(0xffffffffu, rmax0, 2));
        rmax1 = fmaxf(rmax1, __shfl_xor_sync(0xffffffffu, rmax1, 1));
        rmax1 = fmaxf(rmax1, __shfl_xor_sync(0xffffffffu, rmax1, 2));

        float mn0 = fmaxf(m0, rmax0), mn1 = fmaxf(m1, rmax1);
        float corr0 = __expf(m0 - mn0), corr1 = __expf(m1 - mn1);
        float rs0 = 0.0f, rs1 = 0.0f;

#pragma unroll
        for (int nj = 0; nj < 8; nj++) {
            float p0 = __expf(s[nj][0] - mn0);
            float p1 = __expf(s[nj][1] - mn0);
            float p2 = __expf(s[nj][2] - mn1);
            float p3 = __expf(s[nj][3] - mn1);
            rs0 += p0 + p1;
            rs1 += p2 + p3;
            *(uint2*)&Ps[wrow + g][nj * 8 + 2 * t]     = make_uint2(f2tf(p0), f2tf(p1));
            *(uint2*)&Ps[wrow + g + 8][nj * 8 + 2 * t] = make_uint2(f2tf(p2), f2tf(p3));
        }
        rs0 += __shfl_xor_sync(0xffffffffu, rs0, 1);
        rs0 += __shfl_xor_sync(0xffffffffu, rs0, 2);
        rs1 += __shfl_xor_sync(0xffffffffu, rs1, 1);
        rs1 += __shfl_xor_sync(0xffffffffu, rs1, 2);

        l0 = l0 * corr0 + rs0;
        l1 = l1 * corr1 + rs1;
        m0 = mn0; m1 = mn1;
#pragma unroll
        for (int nj = 0; nj < 8; nj++) {
            o[nj][0] *= corr0; o[nj][1] *= corr0;
            o[nj][2] *= corr1; o[nj][3] *= corr1;
        }

        __syncwarp();

#pragma unroll
        for (int ks = 0; ks < 64; ks += 8) {
            unsigned a[4];
            a[0] = Ps[wrow + g][ks + t];
            a[1] = Ps[wrow + g + 8][ks + t];
            a[2] = Ps[wrow + g][ks + t + 4];
            a[3] = Ps[wrow + g + 8][ks + t + 4];
            const int q = (ks >> 1) + t;
#pragma unroll
            for (int nj = 0; nj < 8; nj++) {
                uint2 bv = *(uint2*)(Vsp + (q * FSTR + nj * 8 + g) * 2);
                unsigned bf[2] = { bv.x, bv.y };
                mma8(o[nj], a, bf);
            }
        }
    }

    float inv0 = 1.0f / l0, inv1 = 1.0f / l1;
    int row0 = qt * 128 + wrow + g;
    size_t base0 = ((size_t)b * SS + row0) * DD + h * DHH;
    size_t base1 = base0 + (size_t)8 * DD;
#pragma unroll
    for (int nj = 0; nj < 8; nj++) {
        *(float2*)&O[base0 + nj * 8 + 2 * t] = make_float2(o[nj][0] * inv0, o[nj][1] * inv0);
        *(float2*)&O[base1 + nj * 8 + 2 * t] = make_float2(o[nj][2] * inv1, o[nj][3] * inv1);
    }
}

// ---------------------------------------------------------------------------
// Launch. Inputs (metadata order): key, query, value, valid_lens, Wk, Wq, Wv, Wo
// ---------------------------------------------------------------------------
extern "C" void kernel_launch(void* const* d_in, const int* in_sizes, int n_in,
                              void* d_out, int out_size)
{
    const float* key_   = (const float*)d_in[0];
    const float* query_ = (const float*)d_in[1];
    const float* value_ = (const float*)d_in[2];
    const int*   vlens  = (const int*)  d_in[3];
    const float* Wk     = (const float*)d_in[4];
    const float* Wq     = (const float*)d_in[5];
    const float* Wv     = (const float*)d_in[6];
    const float* Wo     = (const float*)d_in[7];
    float* out = (float*)d_out;

    float *qh, *kh, *vh, *oc;
    unsigned* wt;
    cudaGetSymbolAddress((void**)&qh, g_Qh);
    cudaGetSymbolAddress((void**)&kh, g_Kh);
    cudaGetSymbolAddress((void**)&vh, g_Vh);
    cudaGetSymbolAddress((void**)&oc, g_Oc);
    cudaGetSymbolAddress((void**)&wt, g_Wt);

    cudaFuncSetAttribute(gemm_cp, cudaFuncAttributeMaxDynamicSharedMemorySize,
                         G_SMEM_BYTES);
    cudaFuncSetAttribute(flash_tf32, cudaFuncAttributeMaxDynamicSharedMemorySize,
                         FA_SMEM_BYTES);

    // Pre-convert weights to tf32 bits: order [Wq, Wk, Wv, Wo]
    CArgs ca;
    ca.W[0] = Wq; ca.W[1] = Wk; ca.W[2] = Wv; ca.W[3] = Wo;
    cvt_w<<<dim3(1024, 4), 256>>>(ca, wt);

    // Fused Q/K/V projections (grid z selects operand set)
    GArgs pa;
    pa.A[0] = query_;  pa.A[1] = key_;            pa.A[2] = value_;
    pa.W[0] = wt;      pa.W[1] = wt + (size_t)DD * DD; pa.W[2] = wt + (size_t)2 * DD * DD;
    pa.C[0] = qh;      pa.C[1] = kh;              pa.C[2] = vh;
    pa.mode = 0;
    gemm_cp<<<dim3(DD / 128, MM / 128, 3), 256, G_SMEM_BYTES>>>(pa);

    // b on blockIdx.x so different-vlen CTAs interleave within each wave
    dim3 ga(BB, HH, SS / 128);    // (4, 16, 16)
    flash_tf32<<<ga, 256, FA_SMEM_BYTES>>>(qh, kh, vh, vlens, oc);

    // Output projection (W = Wo tf32)
    GArgs po;
    po.A[0] = po.A[1] = po.A[2] = oc;
    po.W[0] = po.W[1] = po.W[2] = wt + (size_t)3 * DD * DD;
    po.C[0] = po.C[1] = po.C[2] = out;
    po.mode = 1;
    gemm_cp<<<dim3(DD / 128, MM / 128, 1), 256, G_SMEM_BYTES>>>(po);
}

// round 15
// speedup vs baseline: 4.9248x; 1.0530x over previous
#include <cuda_runtime.h>
#include <math.h>
#include <stdint.h>

// Problem constants
#define BB   4
#define SS   2048
#define DD   1024
#define HH   16
#define DHH  64
#define MM   (BB * SS)          // 8192 rows
#define MASKV (-1000000.0f)

// Scratch (device globals: allocation-free rule)
__device__ float    g_Qh[(size_t)MM * DD];  // [B,H,S,DH] head-split
__device__ float    g_Kh[(size_t)MM * DD];
__device__ float    g_Vh[(size_t)MM * DD];
__device__ float    g_Oc[(size_t)MM * DD];  // [B,S,D] concat-head attention output
__device__ unsigned g_Wt[(size_t)4 * DD * DD];  // tf32 quad-layout Wq,Wk,Wv,Wo

// ---------------------------------------------------------------------------
// Helpers
// ---------------------------------------------------------------------------
__device__ __forceinline__ uint32_t smem_u32(const void* p) {
    uint32_t a;
    asm("{ .reg .u64 t; cvta.to.shared.u64 t, %1; cvt.u32.u64 %0, t; }" : "=r"(a) : "l"(p));
    return a;
}
__device__ __forceinline__ unsigned f2tf(float x) {
    unsigned u;
    asm("cvt.rna.tf32.f32 %0, %1;" : "=r"(u) : "f"(x));
    return u;
}
__device__ __forceinline__ void mma8(float* d, const unsigned* a, const unsigned* b) {
    asm volatile(
        "mma.sync.aligned.m16n8k8.row.col.f32.tf32.tf32.f32 "
        "{%0,%1,%2,%3}, {%4,%5,%6,%7}, {%8,%9}, {%0,%1,%2,%3};"
        : "+f"(d[0]), "+f"(d[1]), "+f"(d[2]), "+f"(d[3])
        : "r"(a[0]), "r"(a[1]), "r"(a[2]), "r"(a[3]), "r"(b[0]), "r"(b[1]));
}
__device__ __forceinline__ void cpa16(uint32_t dst, const void* src) {
    asm volatile("cp.async.cg.shared.global [%0], [%1], 16;" :: "r"(dst), "l"(src));
}
#define CPA_COMMIT() asm volatile("cp.async.commit_group;" ::: "memory")
#define CPA_WAIT1()  asm volatile("cp.async.wait_group 1;" ::: "memory")
#define CPA_WAIT0()  asm volatile("cp.async.wait_group 0;" ::: "memory")

// ---------------------------------------------------------------------------
// Weight pre-convert + QUAD re-layout (fp32 -> tf32 bits), once per run.
// Layout: for n-block pair p (n in [16p,16p+16)), k-chunk kc (k in [8kc,8kc+8)):
//   W'[(p*128 + kc)*128 + (g*4 + t)*4 + q]  where n = 16p + 8*(q>>1) + g,
//   k = 8kc + t + 4*(q&1).
// A lane (g,t) then fetches its B-fragments for TWO n-blocks with ONE LDS.128.
// grid (1024, 4) x 256: y selects which W; x*256+tid indexes float4s.
// ---------------------------------------------------------------------------
struct CArgs { const float* W[4]; };

__global__ __launch_bounds__(256) void cvt_w(CArgs a, unsigned* __restrict__ out)
{
    const int w = blockIdx.y;
    const int i = blockIdx.x * 256 + threadIdx.x;       // 0..262143 float4s
    const int n  = i >> 8;                              // row (k0 = (4i) & 1023)
    const int k0 = (i << 2) & 1023;                     // 0,4,8,...
    float4 v = ((const float4*)a.W[w])[i];

    const int p   = n >> 4;
    const int g   = n & 7;
    const int w01 = (n >> 3) & 1;
    const int kc  = k0 >> 3;
    const int hi  = (k0 >> 2) & 1;                      // k0 % 8 is 0 or 4
    unsigned* ob = out + (size_t)w * DD * DD
                 + ((size_t)(p * 128 + kc) * 32 + g * 4) * 4 + (w01 * 2 + hi);
    ob[0]  = f2tf(v.x);     // t = 0
    ob[4]  = f2tf(v.y);     // t = 1
    ob[8]  = f2tf(v.z);     // t = 2
    ob[12] = f2tf(v.w);     // t = 3
}

// ---------------------------------------------------------------------------
// TF32 NT GEMM, 3-stage cp.async pipeline: C[m,n] = sum_k A[m,k] * W[n,k]
// A: fp32 raw (stride-36 smem, cvt at consume). W: quad-layout tf32 bits --
// per k8-step the 8 B-fragments are 4 conflict-free LDS.128.
// 128x128 tile, BK=32, 256 threads (8 warps, warp tile 32x64), 2 CTAs/SM.
// mode 0: head-split [B,H,S,DH]; mode 1: row-major [M,1024]
// ---------------------------------------------------------------------------
struct GArgs { const float* A[3]; const unsigned* W[3]; float* C[3]; int mode; };

#define GBK  32
#define GSTR 36
#define G_A_W  (128 * GSTR)                          // 4608 words
#define G_B_W  4096                                  // 8 pairs x 4 chunks x 128
#define G_STAGE_W (G_A_W + G_B_W)                    // 8704 words per stage
#define G_SMEM_BYTES (3 * G_STAGE_W * 4)             // 104448 B

__global__ __launch_bounds__(256, 2) void gemm_cp(GArgs args)
{
    extern __shared__ float gsm[];
    const uint32_t sb = smem_u32(gsm);
    const int tid  = threadIdx.x;
    const int lane = tid & 31, warp = tid >> 5;
    const int z  = blockIdx.z;
    const float*    __restrict__ A = args.A[z];
    const unsigned* __restrict__ W = args.W[z];
    float* __restrict__ C = args.C[z];
    const int mode = args.mode;
    const int bm = blockIdx.y * 128, bn = blockIdx.x * 128;
    const int wm = (warp >> 1) * 32, wn = (warp & 1) * 64;
    const int g = lane >> 2, t = lane & 3;

    // A staging coords (4 x 16B per thread, stride-36 layout)
    int ar[4], ac[4];
#pragma unroll
    for (int i = 0; i < 4; i++) {
        int idx = tid + i * 256;
        ar[i] = idx >> 3;
        ac[i] = (idx & 7) << 2;
    }
    // B staging coords (4 x 16B per thread, linear copy of quad layout)
    const int b_kcl   = (tid >> 5) & 3;     // k-chunk local, fixed per thread
    const int b_inner = tid & 31;           // 16B unit within 512B block
    const int b_phi   = tid >> 7;           // 0..1

#define G_ISSUE(ktile, stg) do {                                               \
    uint32_t base_ = sb + (uint32_t)(stg) * (G_STAGE_W * 4);                   \
    const float* As_ = A + (size_t)bm * DD + (ktile) * GBK;                    \
    _Pragma("unroll")                                                          \
    for (int i_ = 0; i_ < 4; i_++)                                             \
        cpa16(base_ + (uint32_t)((ar[i_] * GSTR + ac[i_]) * 4),                \
              As_ + (size_t)ar[i_] * DD + ac[i_]);                             \
    _Pragma("unroll")                                                          \
    for (int i_ = 0; i_ < 4; i_++) {                                           \
        int pl_ = b_phi + 2 * i_;                                              \
        int sidx_ = (pl_ * 4 + b_kcl) * 32 + b_inner;   /* 16B units */        \
        const unsigned* Wg_ = W + ((size_t)((bn >> 4) + pl_) * 128             \
                                   + (ktile) * 4 + b_kcl) * 128 + b_inner * 4; \
        cpa16(base_ + (uint32_t)((G_A_W + sidx_ * 4) * 4), Wg_);               \
    }                                                                          \
    CPA_COMMIT();                                                              \
} while (0)

    float acc[2][8][4];
#pragma unroll
    for (int mi = 0; mi < 2; mi++)
#pragma unroll
        for (int nj = 0; nj < 8; nj++)
#pragma unroll
            for (int r = 0; r < 4; r++) acc[mi][nj][r] = 0.0f;

    G_ISSUE(0, 0);
    G_ISSUE(1, 1);

    const int mb0  = wn >> 4;               // 0 or 4: warp's first n-block pair
    const int bfo  = 16 * g + 4 * t;        // lane's word offset within a pair-chunk

    const int NT = DD / GBK;   // 32
    for (int kt = 0; kt < NT; kt++) {
        if (kt < NT - 1) { CPA_WAIT1(); } else { CPA_WAIT0(); }
        __syncthreads();
        if (kt + 2 < NT) G_ISSUE(kt + 2, (kt + 2) % 3);

        const float*    Ast = gsm + (kt % 3) * G_STAGE_W;
        const unsigned* Bst = (const unsigned*)(Ast + G_A_W);
#pragma unroll
        for (int ks = 0; ks < GBK; ks += 8) {
            const int kcl = ks >> 3;
            unsigned a[2][4];
#pragma unroll
            for (int mi = 0; mi < 2; mi++) {
                int r0 = (wm + mi * 16 + g) * GSTR;
                int r8 = (wm + mi * 16 + g + 8) * GSTR;
                a[mi][0] = f2tf(Ast[r0 + ks + t]);
                a[mi][1] = f2tf(Ast[r8 + ks + t]);
                a[mi][2] = f2tf(Ast[r0 + ks + t + 4]);
                a[mi][3] = f2tf(Ast[r8 + ks + t + 4]);
            }
            uint4 bq[4];
#pragma unroll
            for (int p2 = 0; p2 < 4; p2++)
                bq[p2] = *(const uint4*)(Bst + ((mb0 + p2) * 4 + kcl) * 128 + bfo);
#pragma unroll
            for (int mi = 0; mi < 2; mi++)
#pragma unroll
                for (int p2 = 0; p2 < 4; p2++) {
                    unsigned b0[2] = { bq[p2].x, bq[p2].y };
                    mma8(acc[mi][2 * p2], a[mi], b0);
                    unsigned b1[2] = { bq[p2].z, bq[p2].w };
                    mma8(acc[mi][2 * p2 + 1], a[mi], b1);
                }
        }
    }
#undef G_ISSUE

    if (mode == 0) {
#pragma unroll
        for (int mi = 0; mi < 2; mi++)
#pragma unroll
            for (int rr = 0; rr < 2; rr++) {
                int m  = bm + wm + mi * 16 + g + rr * 8;
                int b_ = m >> 11;
                int s_ = m & (SS - 1);
#pragma unroll
                for (int nj = 0; nj < 8; nj++) {
                    int n  = bn + wn + nj * 8 + 2 * t;
                    int h_ = n >> 6;
                    int dh = n & 63;
                    float2 v = make_float2(acc[mi][nj][rr * 2], acc[mi][nj][rr * 2 + 1]);
                    *(float2*)&C[(((size_t)b_ * HH + h_) * SS + s_) * DHH + dh] = v;
                }
            }
    } else {
#pragma unroll
        for (int mi = 0; mi < 2; mi++)
#pragma unroll
            for (int rr = 0; rr < 2; rr++) {
                int m = bm + wm + mi * 16 + g + rr * 8;
#pragma unroll
                for (int nj = 0; nj < 8; nj++) {
                    int n = bn + wn + nj * 8 + 2 * t;
                    float2 v = make_float2(acc[mi][nj][rr * 2], acc[mi][nj][rr * 2 + 1]);
                    *(float2*)&C[(size_t)m * DD + n] = v;
                }
            }
    }
}

// ---------------------------------------------------------------------------
// TF32 flash attention v3 — byte-identical to the R12/R13 passing version.
// ---------------------------------------------------------------------------
#define FSTR 68
#define FQ_W 0
#define FK_W 8704
#define FV_W (8704 + 4352)
#define FP_W (8704 + 4352 + 4352)
#define FA_SMEM_BYTES ((8704 + 4352 + 4352 + 8704) * 4)   // 104448 B

__global__ __launch_bounds__(256) void flash_tf32(const float* __restrict__ Q,
                                                  const float* __restrict__ K,
                                                  const float* __restrict__ V,
                                                  const int* __restrict__ vlens,
                                                  float* __restrict__ O)
{
    extern __shared__ unsigned sm[];
    unsigned (*Qs)[FSTR] = (unsigned (*)[FSTR])(sm + FQ_W);
    unsigned (*Ks)[FSTR] = (unsigned (*)[FSTR])(sm + FK_W);
    unsigned* Vsp        = sm + FV_W;   // VP[q][c] uint2 pairs, q-stride 68
    unsigned (*Ps)[FSTR] = (unsigned (*)[FSTR])(sm + FP_W);

    const int tid  = threadIdx.x;
    const int lane = tid & 31, warp = tid >> 5;
    const int b = blockIdx.x, h = blockIdx.y, qt = blockIdx.z;
    const int head = b * HH + h;

    const float* Qb = Q + ((size_t)head * SS + qt * 128) * DHH;
    const float* Kb = K + (size_t)head * SS * DHH;
    const float* Vb = V + (size_t)head * SS * DHH;
    const int   vlen = vlens[b];
    const int   g = lane >> 2, t = lane & 3;
    const int   wrow = warp * 16;
    const float scale = 0.125f;

#pragma unroll
    for (int it = 0; it < 8; it++) {
        int idx = tid + it * 256;
        int row = idx >> 4;
        int c   = (idx & 15) << 2;
        float4 v = *(const float4*)(Qb + (size_t)row * DHH + c);
        *(uint4*)&Qs[row][c] = make_uint4(f2tf(v.x), f2tf(v.y), f2tf(v.z), f2tf(v.w));
    }

    float o[8][4];
#pragma unroll
    for (int nj = 0; nj < 8; nj++)
#pragma unroll
        for (int r = 0; r < 4; r++) o[nj][r] = 0.0f;
    float m0 = -1e30f, m1 = -1e30f, l0 = 0.0f, l1 = 0.0f;

    const int nb = (vlen == 0) ? (SS / 64) : ((vlen + 63) >> 6);

    for (int kbi = 0; kbi < nb; kbi++) {
        const int kb = kbi * 64;
        __syncthreads();
#pragma unroll
        for (int it = 0; it < 4; it++) {
            int idx = tid + it * 256;
            int row = idx >> 4;
            int c   = (idx & 15) << 2;
            float4 vk = *(const float4*)(Kb + (size_t)(kb + row) * DHH + c);
            *(uint4*)&Ks[row][c] = make_uint4(f2tf(vk.x), f2tf(vk.y), f2tf(vk.z), f2tf(vk.w));
        }
#pragma unroll
        for (int it = 0; it < 2; it++) {
            int u  = tid + it * 256;
            int q  = u >> 4;
            int c  = (u & 15) << 2;
            int r0 = ((q >> 2) << 3) + (q & 3);
            const float* Vr = Vb + (size_t)(kb + r0) * DHH + c;
            float4 v0 = *(const float4*)(Vr);
            float4 v1 = *(const float4*)(Vr + 4 * DHH);
            unsigned* base = Vsp + (q * FSTR + c) * 2;
            *(uint2*)(base + 0) = make_uint2(f2tf(v0.x), f2tf(v1.x));
            *(uint2*)(base + 2) = make_uint2(f2tf(v0.y), f2tf(v1.y));
            *(uint2*)(base + 4) = make_uint2(f2tf(v0.z), f2tf(v1.z));
            *(uint2*)(base + 6) = make_uint2(f2tf(v0.w), f2tf(v1.w));
        }
        __syncthreads();

        float s[8][4];
#pragma unroll
        for (int nj = 0; nj < 8; nj++)
#pragma unroll
            for (int r = 0; r < 4; r++) s[nj][r] = 0.0f;

#pragma unroll
        for (int ks = 0; ks < DHH; ks += 8) {
            unsigned a[4];
            a[0] = Qs[wrow + g][ks + t];
            a[1] = Qs[wrow + g + 8][ks + t];
            a[2] = Qs[wrow + g][ks + t + 4];
            a[3] = Qs[wrow + g + 8][ks + t + 4];
#pragma unroll
            for (int nj = 0; nj < 8; nj++) {
                unsigned bf[2];
                bf[0] = Ks[nj * 8 + g][ks + t];
                bf[1] = Ks[nj * 8 + g][ks + t + 4];
                mma8(s[nj], a, bf);
            }
        }

        float rmax0 = -1e30f, rmax1 = -1e30f;
#pragma unroll
        for (int nj = 0; nj < 8; nj++) {
            int c0 = kb + nj * 8 + 2 * t;
            bool v0 = c0 < vlen, v1 = (c0 + 1) < vlen;
            s[nj][0] = v0 ? s[nj][0] * scale : MASKV;
            s[nj][1] = v1 ? s[nj][1] * scale : MASKV;
            s[nj][2] = v0 ? s[nj][2] * scale : MASKV;
            s[nj][3] = v1 ? s[nj][3] * scale : MASKV;
            rmax0 = fmaxf(rmax0, fmaxf(s[nj][0], s[nj][1]));
            rmax1 = fmaxf(rmax1, fmaxf(s[nj][2], s[nj][3]));
        }
        rmax0 = fmaxf(rmax0, __shfl_xor_sync(0xffffffffu, rmax0, 1));
        rmax0 = fmaxf(rmax0, __shfl_xor_sync(0xffffffffu, rmax0, 2));
        rmax1 = fmaxf(rmax1, __shfl_xor_sync(0xffffffffu, rmax1, 1));
        rmax1 = fmaxf(rmax1, __shfl_xor_sync(0xffffffffu, rmax1, 2));

        float mn0 = fmaxf(m0, rmax0), mn1 = fmaxf(m1, rmax1);
        float corr0 = __expf(m0 - mn0), corr1 = __expf(m1 - mn1);
        float rs0 = 0.0f, rs1 = 0.0f;

#pragma unroll
        for (int nj = 0; nj < 8; nj++) {
            float p0 = __expf(s[nj][0] - mn0);
            float p1 = __expf(s[nj][1] - mn0);
            float p2 = __expf(s[nj][2] - mn1);
            float p3 = __expf(s[nj][3] - mn1);
            rs0 += p0 + p1;
            rs1 += p2 + p3;
            *(uint2*)&Ps[wrow + g][nj * 8 + 2 * t]     = make_uint2(f2tf(p0), f2tf(p1));
            *(uint2*)&Ps[wrow + g + 8][nj * 8 + 2 * t] = make_uint2(f2tf(p2), f2tf(p3));
        }
        rs0 += __shfl_xor_sync(0xffffffffu, rs0, 1);
        rs0 += __shfl_xor_sync(0xffffffffu, rs0, 2);
        rs1 += __shfl_xor_sync(0xffffffffu, rs1, 1);
        rs1 += __shfl_xor_sync(0xffffffffu, rs1, 2);

        l0 = l0 * corr0 + rs0;
        l1 = l1 * corr1 + rs1;
        m0 = mn0; m1 = mn1;
#pragma unroll
        for (int nj = 0; nj < 8; nj++) {
            o[nj][0] *= corr0; o[nj][1] *= corr0;
            o[nj][2] *= corr1; o[nj][3] *= corr1;
        }

        __syncwarp();

#pragma unroll
        for (int ks = 0; ks < 64; ks += 8) {
            unsigned a[4];
            a[0] = Ps[wrow + g][ks + t];
            a[1] = Ps[wrow + g + 8][ks + t];
            a[2] = Ps[wrow + g][ks + t + 4];
            a[3] = Ps[wrow + g + 8][ks + t + 4];
            const int q = (ks >> 1) + t;
#pragma unroll
            for (int nj = 0; nj < 8; nj++) {
                uint2 bv = *(uint2*)(Vsp + (q * FSTR + nj * 8 + g) * 2);
                unsigned bf[2] = { bv.x, bv.y };
                mma8(o[nj], a, bf);
            }
        }
    }

    float inv0 = 1.0f / l0, inv1 = 1.0f / l1;
    int row0 = qt * 128 + wrow + g;
    size_t base0 = ((size_t)b * SS + row0) * DD + h * DHH;
    size_t base1 = base0 + (size_t)8 * DD;
#pragma unroll
    for (int nj = 0; nj < 8; nj++) {
        *(float2*)&O[base0 + nj * 8 + 2 * t] = make_float2(o[nj][0] * inv0, o[nj][1] * inv0);
        *(float2*)&O[base1 + nj * 8 + 2 * t] = make_float2(o[nj][2] * inv1, o[nj][3] * inv1);
    }
}

// ---------------------------------------------------------------------------
// Launch. Inputs (metadata order): key, query, value, valid_lens, Wk, Wq, Wv, Wo
// ---------------------------------------------------------------------------
extern "C" void kernel_launch(void* const* d_in, const int* in_sizes, int n_in,
                              void* d_out, int out_size)
{
    const float* key_   = (const float*)d_in[0];
    const float* query_ = (const float*)d_in[1];
    const float* value_ = (const float*)d_in[2];
    const int*   vlens  = (const int*)  d_in[3];
    const float* Wk     = (const float*)d_in[4];
    const float* Wq     = (const float*)d_in[5];
    const float* Wv     = (const float*)d_in[6];
    const float* Wo     = (const float*)d_in[7];
    float* out = (float*)d_out;

    float *qh, *kh, *vh, *oc;
    unsigned* wt;
    cudaGetSymbolAddress((void**)&qh, g_Qh);
    cudaGetSymbolAddress((void**)&kh, g_Kh);
    cudaGetSymbolAddress((void**)&vh, g_Vh);
    cudaGetSymbolAddress((void**)&oc, g_Oc);
    cudaGetSymbolAddress((void**)&wt, g_Wt);

    cudaFuncSetAttribute(gemm_cp, cudaFuncAttributeMaxDynamicSharedMemorySize,
                         G_SMEM_BYTES);
    cudaFuncSetAttribute(flash_tf32, cudaFuncAttributeMaxDynamicSharedMemorySize,
                         FA_SMEM_BYTES);

    // Pre-convert weights to quad-layout tf32 bits: order [Wq, Wk, Wv, Wo]
    CArgs ca;
    ca.W[0] = Wq; ca.W[1] = Wk; ca.W[2] = Wv; ca.W[3] = Wo;
    cvt_w<<<dim3(1024, 4), 256>>>(ca, wt);

    // Fused Q/K/V projections (grid z selects operand set)
    GArgs pa;
    pa.A[0] = query_;  pa.A[1] = key_;                 pa.A[2] = value_;
    pa.W[0] = wt;      pa.W[1] = wt + (size_t)DD * DD; pa.W[2] = wt + (size_t)2 * DD * DD;
    pa.C[0] = qh;      pa.C[1] = kh;                   pa.C[2] = vh;
    pa.mode = 0;
    gemm_cp<<<dim3(DD / 128, MM / 128, 3), 256, G_SMEM_BYTES>>>(pa);

    // b on blockIdx.x so different-vlen CTAs interleave within each wave
    dim3 ga(BB, HH, SS / 128);    // (4, 16, 16)
    flash_tf32<<<ga, 256, FA_SMEM_BYTES>>>(qh, kh, vh, vlens, oc);

    // Output projection (W = Wo quad tf32)
    GArgs po;
    po.A[0] = po.A[1] = po.A[2] = oc;
    po.W[0] = po.W[1] = po.W[2] = wt + (size_t)3 * DD * DD;
    po.C[0] = po.C[1] = po.C[2] = out;
    po.mode = 1;
    gemm_cp<<<dim3(DD / 128, MM / 128, 1), 256, G_SMEM_BYTES>>>(po);
}